// round 6
// baseline (speedup 1.0000x reference)
#include <cuda_runtime.h>
#include <cstdint>
#include <cstddef>

#define NN 100000
#define NE 600000
#define H 128
#define FIN 39

#define BM 128
#define BN 128
#define BK 32

// ---------------- scratch (device globals; no allocation allowed) ----------------
__device__ float g_h[(size_t)NN * H];        // node features          [N,128]
__device__ float g_PQ[(size_t)NN * 4 * H];   // P_a|Q_a|P_e|Q_e        [N,512]
__device__ float g_S[(size_t)NN * 2 * H];    // S_ally | S_enc         [N,256]
__device__ float g_deg[2 * NN];              // deg_ally, deg_enc (as float)
// pair-duplicated weights [k][2c]=[k][2c+1]=W[k][c]:
//   units 0..7 : gemm0 (layer i, y)           at (i*4+y)*32768
//   units 8..11: gemm1 ([W2a;W2e] per layer)  at 8*32768 + i*65536 (+ half*32768)
//   units 12,13: gemm2 (comb_W per layer)     at 8*32768 + 2*65536 + i*32768
__device__ float g_wd[14 * 128 * 256];

#define WD_G1 (8 * 32768)
#define WD_G2 (8 * 32768 + 2 * 65536)

__device__ __forceinline__ void cp16(uint32_t dst, const float* src) {
    asm volatile("cp.async.cg.shared.global [%0], [%1], 16;" :: "r"(dst), "l"(src));
}
__device__ __forceinline__ void ffma2(unsigned long long& d, unsigned long long a,
                                      unsigned long long b) {
    asm("fma.rn.f32x2 %0, %1, %2, %0;" : "+l"(d) : "l"(a), "l"(b));
}
__device__ __forceinline__ void unpack2(unsigned long long v, float& lo, float& hi) {
    asm("mov.b64 {%0, %1}, %2;" : "=f"(lo), "=f"(hi) : "l"(v));
}

// ---------------- utility kernels ----------------
__global__ void fill_zero(float4* __restrict__ p, int n4) {
    int i = blockIdx.x * blockDim.x + threadIdx.x;
    int stride = gridDim.x * blockDim.x;
    float4 z = make_float4(0.f, 0.f, 0.f, 0.f);
    for (; i < n4; i += stride) p[i] = z;
}

__global__ void deg_kernel(const int* __restrict__ eia, const int* __restrict__ eie,
                           float* __restrict__ deg) {
    int t = blockIdx.x * blockDim.x + threadIdx.x;
    if (t < NE) {
        atomicAdd(&deg[eia[NE + t]], 1.f);
    } else if (t < 2 * NE) {
        atomicAdd(&deg[NN + eie[NE + (t - NE)]], 1.f);
    }
}

// pair-duplicate all 14 unit weight matrices into g_wd
__global__ void prep_dup(const float* __restrict__ aW1, const float* __restrict__ eW1,
                         const float* __restrict__ aW2, const float* __restrict__ eW2,
                         const float* __restrict__ combW, float* __restrict__ wd) {
    int idx = blockIdx.x * blockDim.x + threadIdx.x;
    if (idx >= 14 * 16384) return;
    int u = idx >> 14;
    int rem = idx & 16383;
    int k = rem >> 7;
    int c = rem & 127;
    float v;
    size_t dst;
    if (u < 8) {
        int i = u >> 2, y = u & 3;
        const float* base = (y < 2 ? aW1 : eW1) + (size_t)i * 258 * H + (size_t)(y & 1) * 128 * H;
        v = base[k * H + c];
        dst = (size_t)u * 32768;
    } else if (u < 12) {
        int i = (u - 8) >> 1, half = (u - 8) & 1;
        const float* base = (half == 0 ? aW2 : eW2) + (size_t)i * H * H;
        v = base[k * H + c];
        dst = (size_t)WD_G1 + (size_t)i * 65536 + (size_t)half * 32768;
    } else {
        int i = u - 12;
        v = combW[(size_t)i * H * H + k * H + c];
        dst = (size_t)WD_G2 + (size_t)i * 32768;
    }
    wd[dst + (size_t)k * 256 + 2 * c] = v;
    wd[dst + (size_t)k * 256 + 2 * c + 1] = v;
}

// ---------------- input projection: h = relu(x @ W_in + b_in) ----------------
#define IPN 16
__global__ void __launch_bounds__(128) input_proj(const float* __restrict__ x,
                                                  const float* __restrict__ Win,
                                                  const float* __restrict__ bin,
                                                  float* __restrict__ h) {
    __shared__ float Ws[FIN * H];
    __shared__ float xs[IPN][FIN + 1];
    int tid = threadIdx.x;
    for (int i = tid; i < FIN * H; i += 128) Ws[i] = Win[i];
    int n0 = blockIdx.x * IPN;
    for (int i = tid; i < IPN * FIN; i += 128) {
        int r = i / FIN, c = i - r * FIN;
        xs[r][c] = x[(size_t)(n0 + r) * FIN + c];
    }
    __syncthreads();
    float acc[IPN];
    float bv = bin[tid];
#pragma unroll
    for (int r = 0; r < IPN; r++) acc[r] = bv;
    for (int k = 0; k < FIN; k++) {
        float wv = Ws[k * H + tid];
#pragma unroll
        for (int r = 0; r < IPN; r++) acc[r] = fmaf(xs[r][k], wv, acc[r]);
    }
#pragma unroll
    for (int r = 0; r < IPN; r++)
        h[(size_t)(n0 + r) * H + tid] = fmaxf(acc[r], 0.f);
}

// ---------------- edge phase: one edge set per launch (L2 locality) ----------------
// warp per edge: S[tgt] += relu(P[tgt] + Q[src] + ea @ W1c)
__global__ void __launch_bounds__(256) edge_kernel(const int* __restrict__ ei,
                                                   const float* __restrict__ ea,
                                                   const float* __restrict__ PQ, int pq_off,
                                                   const float* __restrict__ w1c,
                                                   float* __restrict__ S, int s_off) {
    __shared__ __align__(16) float w[2 * H];
    if (threadIdx.x < 2 * H) w[threadIdx.x] = w1c[threadIdx.x];
    __syncthreads();
    int e = (blockIdx.x * 256 + threadIdx.x) >> 5;
    int lane = threadIdx.x & 31;
    int src = ei[e];
    int tgt = ei[NE + e];
    float e0 = ea[2 * e], e1 = ea[2 * e + 1];
    float4 p = *(const float4*)&PQ[(size_t)tgt * 512 + pq_off + lane * 4];
    float4 q = *(const float4*)&PQ[(size_t)src * 512 + pq_off + 128 + lane * 4];
    float4 w0 = *(const float4*)&w[lane * 4];
    float4 w1 = *(const float4*)&w[H + lane * 4];
    float4 t;
    t.x = fmaxf(fmaf(e0, w0.x, fmaf(e1, w1.x, p.x + q.x)), 0.f);
    t.y = fmaxf(fmaf(e0, w0.y, fmaf(e1, w1.y, p.y + q.y)), 0.f);
    t.z = fmaxf(fmaf(e0, w0.z, fmaf(e1, w1.z, p.z + q.z)), 0.f);
    t.w = fmaxf(fmaf(e0, w0.w, fmaf(e1, w1.w, p.w + q.w)), 0.f);
    float* dst = &S[(size_t)tgt * 256 + s_off + lane * 4];
    asm volatile("red.global.add.v4.f32 [%0], {%1,%2,%3,%4};"
                 :: "l"(dst), "f"(t.x), "f"(t.y), "f"(t.z), "f"(t.w) : "memory");
}

// ---------------- 128x128 SGEMM, 128 threads, 16x8 micro-tile, FFMA2 + pre-dup B --------------
// B comes from g_wd pair-duplicated [Ktot][256] -> b operands load as u64 pairs, no packs.
// MODE 0 (PQ):      out[:, y*128:(y+1)*128] = h @ B[y] (+bias y==0,2); y==0 zeroes S
// MODE 1 (COMBINE): u = S@[W2a;W2e] + h + dega*b2a + dege*b2e; h = LayerNorm(u)
// MODE 2 (COMB):    out = resid + relu(h @ B + bias0)
template <int MODE>
__global__ void __launch_bounds__(128, 2) gemm_kernel(
    const float* __restrict__ A, int lda, int Ktot,
    const float* __restrict__ Bd,       // duplicated [Ktot][256] (MODE0: base of 4 units)
    const float* __restrict__ bias0, const float* __restrict__ bias2,
    const float* __restrict__ resid,
    const float* __restrict__ dega, const float* __restrict__ dege,
    const float* __restrict__ b2a, const float* __restrict__ b2e,
    const float* __restrict__ lng, const float* __restrict__ lnb,
    float* __restrict__ out, int ldo,
    float* __restrict__ Szero) {
    extern __shared__ float sm[];
    float(*As)[BK][BM + 4] = (float(*)[BK][BM + 4])sm;                    // [2][32][132]
    float(*Bsd)[BK][2 * BN] = (float(*)[BK][2 * BN])(sm + 2 * BK * (BM + 4));  // [2][32][256]

    int tid = threadIdx.x;
    int tx = tid & 15;   // col group (8 cols)
    int ty = tid >> 4;   // row group (16 rows)
    int row0 = blockIdx.x * BM;

    const float* B = Bd;
    const float* bias = bias0;
    int ocol = 0;
    if (MODE == 0) {
        int y = blockIdx.y;
        B = Bd + (size_t)y * 32768;
        bias = (y == 0) ? bias0 : (y == 2) ? bias2 : nullptr;
        ocol = y * BN;
    }

    // A staging: one row per thread (32 floats = 8 float4), transposed store
    int agr = row0 + tid;
    bool aval = agr < NN;
    const float* Aptr = A + (size_t)(aval ? agr : 0) * lda;
    // B staging: per thread 4 k-rows (bk0+8i), 16 duplicated floats each (4 cp16)
    int bk0 = tid >> 4;        // 0..7
    int bc = (tid & 15) * 16;  // 0..240

    uint32_t bs_base = (uint32_t)__cvta_generic_to_shared(&Bsd[0][0][0]);

    // prologue: B(0) -> buf0, A(0) -> regs
#pragma unroll
    for (int i = 0; i < 4; i++) {
        int k = bk0 + i * 8;
        const float* s = B + (size_t)k * 256 + bc;
        uint32_t d = bs_base + (unsigned)(k * 256 + bc) * 4u;
        cp16(d, s);
        cp16(d + 16, s + 4);
        cp16(d + 32, s + 8);
        cp16(d + 48, s + 12);
    }
    asm volatile("cp.async.commit_group;" ::: "memory");

    float4 pa[8];
#pragma unroll
    for (int j = 0; j < 8; j++) pa[j] = *(const float4*)(Aptr + j * 4);

    unsigned long long acc[8][8];  // row-pair x col, packed f32x2
#pragma unroll
    for (int rp = 0; rp < 8; rp++)
#pragma unroll
        for (int c = 0; c < 8; c++) acc[rp][c] = 0ull;

    const int niter = Ktot / BK;
    for (int it = 0; it < niter; it++) {
        int buf = it & 1;
        asm volatile("cp.async.wait_group 0;" ::: "memory");
        // commit A regs -> As[buf] (transposed)
#pragma unroll
        for (int j = 0; j < 8; j++) {
            int k0 = j * 4;
            As[buf][k0 + 0][tid] = pa[j].x;
            As[buf][k0 + 1][tid] = pa[j].y;
            As[buf][k0 + 2][tid] = pa[j].z;
            As[buf][k0 + 3][tid] = pa[j].w;
        }
        // prefetch next A into regs
        if (it + 1 < niter) {
            const float* ap = Aptr + (it + 1) * BK;
#pragma unroll
            for (int j = 0; j < 8; j++) pa[j] = *(const float4*)(ap + j * 4);
        }
        __syncthreads();
        // issue next B tile into the other buffer
        if (it + 1 < niter) {
            int kk = (it + 1) * BK;
            uint32_t bb = bs_base + (unsigned)((buf ^ 1) * BK * 256) * 4u;
#pragma unroll
            for (int i = 0; i < 4; i++) {
                int k = bk0 + i * 8;
                const float* s = B + (size_t)(kk + k) * 256 + bc;
                uint32_t d = bb + (unsigned)(k * 256 + bc) * 4u;
                cp16(d, s);
                cp16(d + 16, s + 4);
                cp16(d + 32, s + 8);
                cp16(d + 48, s + 12);
            }
            asm volatile("cp.async.commit_group;" ::: "memory");
        }
        // compute: FFMA2, rows packed in pairs; b pre-duplicated (no packs)
#pragma unroll 4
        for (int k = 0; k < BK; k++) {
            unsigned long long a2[8];
            const ulonglong2* arow = (const ulonglong2*)&As[buf][k][ty * 16];
#pragma unroll
            for (int j = 0; j < 4; j++) {
                ulonglong2 v = arow[j];
                a2[j * 2] = v.x;
                a2[j * 2 + 1] = v.y;
            }
            unsigned long long bp[8];
            const ulonglong2* brow = (const ulonglong2*)&Bsd[buf][k][tx * 16];
#pragma unroll
            for (int j = 0; j < 4; j++) {
                ulonglong2 v = brow[j];
                bp[j * 2] = v.x;
                bp[j * 2 + 1] = v.y;
            }
#pragma unroll
            for (int rp = 0; rp < 8; rp++)
#pragma unroll
                for (int c = 0; c < 8; c++) ffma2(acc[rp][c], a2[rp], bp[c]);
        }
    }

    int col0 = tx * 8;
    const float4 z4 = make_float4(0.f, 0.f, 0.f, 0.f);
    if (MODE == 0) {
        float bv[8];
#pragma unroll
        for (int c = 0; c < 8; c++) bv[c] = bias ? bias[col0 + c] : 0.f;
#pragma unroll
        for (int rp = 0; rp < 8; rp++) {
            float vlo[8], vhi[8];
#pragma unroll
            for (int c = 0; c < 8; c++) unpack2(acc[rp][c], vlo[c], vhi[c]);
            int gr0 = row0 + ty * 16 + rp * 2;
#pragma unroll
            for (int h2 = 0; h2 < 2; h2++) {
                int gr = gr0 + h2;
                const float* v = h2 ? vhi : vlo;
                if (gr < NN) {
                    float o[8];
#pragma unroll
                    for (int c = 0; c < 8; c++) o[c] = v[c] + bv[c];
                    *(float4*)&out[(size_t)gr * ldo + ocol + col0] = *(float4*)o;
                    *(float4*)&out[(size_t)gr * ldo + ocol + col0 + 4] = *(float4*)(o + 4);
                }
            }
        }
        if (blockIdx.y == 0 && Szero) {
#pragma unroll
            for (int r = 0; r < 16; r++) {
                int gr = row0 + ty * 16 + r;
                if (gr < NN) {
                    float4* dst = (float4*)&Szero[(size_t)gr * 256 + tx * 16];
                    dst[0] = z4; dst[1] = z4; dst[2] = z4; dst[3] = z4;
                }
            }
        }
    } else if (MODE == 2) {
        float bv[8];
#pragma unroll
        for (int c = 0; c < 8; c++) bv[c] = bias0[col0 + c];
#pragma unroll
        for (int rp = 0; rp < 8; rp++) {
            float vlo[8], vhi[8];
#pragma unroll
            for (int c = 0; c < 8; c++) unpack2(acc[rp][c], vlo[c], vhi[c]);
            int gr0 = row0 + ty * 16 + rp * 2;
#pragma unroll
            for (int h2 = 0; h2 < 2; h2++) {
                int gr = gr0 + h2;
                const float* v = h2 ? vhi : vlo;
                if (gr < NN) {
                    float o[8];
#pragma unroll
                    for (int c = 0; c < 8; c++) {
                        float t = fmaxf(v[c] + bv[c], 0.f);
                        o[c] = t + resid[(size_t)gr * H + col0 + c];
                    }
                    *(float4*)&out[(size_t)gr * ldo + col0] = *(float4*)o;
                    *(float4*)&out[(size_t)gr * ldo + col0 + 4] = *(float4*)(o + 4);
                }
            }
        }
    } else {
        // MODE 1: residual + deg*b2, LayerNorm via 16-lane shuffle reduction
        float b2av[8], b2ev[8], gv[8], bbv[8];
        *(float4*)&b2av[0] = *(const float4*)&b2a[col0];
        *(float4*)&b2av[4] = *(const float4*)&b2a[col0 + 4];
        *(float4*)&b2ev[0] = *(const float4*)&b2e[col0];
        *(float4*)&b2ev[4] = *(const float4*)&b2e[col0 + 4];
        *(float4*)&gv[0] = *(const float4*)&lng[col0];
        *(float4*)&gv[4] = *(const float4*)&lng[col0 + 4];
        *(float4*)&bbv[0] = *(const float4*)&lnb[col0];
        *(float4*)&bbv[4] = *(const float4*)&lnb[col0 + 4];
#pragma unroll
        for (int rp = 0; rp < 8; rp++) {
            float vlo[8], vhi[8];
#pragma unroll
            for (int c = 0; c < 8; c++) unpack2(acc[rp][c], vlo[c], vhi[c]);
            int gr0 = row0 + ty * 16 + rp * 2;
#pragma unroll
            for (int h2 = 0; h2 < 2; h2++) {
                int gr = gr0 + h2;
                float* vv = h2 ? vhi : vlo;
                bool valid = gr < NN;
                float da = valid ? dega[gr] : 0.f;
                float de = valid ? dege[gr] : 0.f;
                float rs[8];
                if (valid) {
                    *(float4*)&rs[0] = *(const float4*)&resid[(size_t)gr * H + col0];
                    *(float4*)&rs[4] = *(const float4*)&resid[(size_t)gr * H + col0 + 4];
                } else {
#pragma unroll
                    for (int c = 0; c < 8; c++) rs[c] = 0.f;
                }
                float v[8];
                float s = 0.f, s2 = 0.f;
#pragma unroll
                for (int c = 0; c < 8; c++) {
                    v[c] = vv[c] + rs[c] + da * b2av[c] + de * b2ev[c];
                    s += v[c];
                    s2 += v[c] * v[c];
                }
#pragma unroll
                for (int off = 8; off; off >>= 1) {
                    s += __shfl_xor_sync(0xffffffffu, s, off);
                    s2 += __shfl_xor_sync(0xffffffffu, s2, off);
                }
                float mu = s * (1.f / 128.f);
                float var = s2 * (1.f / 128.f) - mu * mu;
                float rstd = rsqrtf(var + 1e-5f);
                if (valid) {
                    float o[8];
#pragma unroll
                    for (int c = 0; c < 8; c++) o[c] = (v[c] - mu) * rstd * gv[c] + bbv[c];
                    *(float4*)&out[(size_t)gr * H + col0] = *(float4*)o;
                    *(float4*)&out[(size_t)gr * H + col0 + 4] = *(float4*)(o + 4);
                }
            }
        }
    }
}

// ---------------- launch ----------------
extern "C" void kernel_launch(void* const* d_in, const int* in_sizes, int n_in,
                              void* d_out, int out_size) {
    (void)in_sizes; (void)n_in; (void)out_size;
    const float* x       = (const float*)d_in[0];
    const int*   ally_ei = (const int*)d_in[1];
    const float* ally_ea = (const float*)d_in[2];
    const int*   enc_ei  = (const int*)d_in[3];
    const float* enc_ea  = (const float*)d_in[4];
    const float* W_in    = (const float*)d_in[5];
    const float* b_in    = (const float*)d_in[6];
    const float* ally_W1 = (const float*)d_in[7];
    const float* ally_b1 = (const float*)d_in[8];
    const float* ally_W2 = (const float*)d_in[9];
    const float* ally_b2 = (const float*)d_in[10];
    const float* enc_W1  = (const float*)d_in[11];
    const float* enc_b1  = (const float*)d_in[12];
    const float* enc_W2  = (const float*)d_in[13];
    const float* enc_b2  = (const float*)d_in[14];
    const float* ln_g    = (const float*)d_in[15];
    const float* ln_b    = (const float*)d_in[16];
    const float* comb_W  = (const float*)d_in[17];
    const float* comb_b  = (const float*)d_in[18];
    float* out = (float*)d_out;

    float *h, *PQ, *S, *deg, *wd;
    cudaGetSymbolAddress((void**)&h, g_h);
    cudaGetSymbolAddress((void**)&PQ, g_PQ);
    cudaGetSymbolAddress((void**)&S, g_S);
    cudaGetSymbolAddress((void**)&deg, g_deg);
    cudaGetSymbolAddress((void**)&wd, g_wd);
    float* dega = deg;
    float* dege = deg + NN;

    const int SMEM = (2 * BK * (BM + 4) + 2 * BK * 2 * BN) * 4;  // 99328 B
    cudaFuncSetAttribute(gemm_kernel<0>, cudaFuncAttributeMaxDynamicSharedMemorySize, SMEM);
    cudaFuncSetAttribute(gemm_kernel<1>, cudaFuncAttributeMaxDynamicSharedMemorySize, SMEM);
    cudaFuncSetAttribute(gemm_kernel<2>, cudaFuncAttributeMaxDynamicSharedMemorySize, SMEM);

    const int nblk = (NN + BM - 1) / BM;  // 782

    // degree (recomputed every call for determinism)
    fill_zero<<<64, 256>>>((float4*)deg, 2 * NN / 4);
    deg_kernel<<<(2 * NE + 255) / 256, 256>>>(ally_ei, enc_ei, deg);

    // pair-duplicate all weights
    prep_dup<<<(14 * 16384 + 255) / 256, 256>>>(ally_W1, enc_W1, ally_W2, enc_W2, comb_W, wd);

    // input projection
    input_proj<<<NN / IPN, 128>>>(x, W_in, b_in, h);

    for (int i = 0; i < 2; i++) {
        const float* aW1 = ally_W1 + (size_t)i * 258 * H;
        const float* eW1 = enc_W1 + (size_t)i * 258 * H;

        // P/Q for both edge types; y==0 blocks additionally zero S
        gemm_kernel<0><<<dim3(nblk, 4), 128, SMEM>>>(
            h, H, H,
            wd + (size_t)i * 4 * 32768,
            ally_b1 + i * H, enc_b1 + i * H,
            nullptr, nullptr, nullptr, nullptr, nullptr, nullptr, nullptr,
            PQ, 4 * H, S);

        // edge scatter: one edge set per launch (smaller L2 working set)
        edge_kernel<<<NE / 8, 256>>>(ally_ei, ally_ea, PQ, 0, aW1 + 256 * H, S, 0);
        edge_kernel<<<NE / 8, 256>>>(enc_ei, enc_ea, PQ, 256, eW1 + 256 * H, S, 128);

        // combine: h = LN(h + S_a@W2a + dega*b2a + S_e@W2e + dege*b2e)
        gemm_kernel<1><<<nblk, 128, SMEM>>>(
            S, 2 * H, 2 * H,
            wd + WD_G1 + (size_t)i * 65536,
            nullptr, nullptr,
            h, dega, dege,
            ally_b2 + i * H, enc_b2 + i * H,
            ln_g + i * H, ln_b + i * H,
            h, H, nullptr);

        // comb MLP: h = h + relu(h @ comb_W + comb_b); last layer writes d_out
        float* dst = (i == 1) ? out : h;
        gemm_kernel<2><<<nblk, 128, SMEM>>>(
            h, H, H,
            wd + WD_G2 + (size_t)i * 32768,
            comb_b + i * H, nullptr,
            h, nullptr, nullptr, nullptr, nullptr, nullptr, nullptr,
            dst, H, nullptr);
    }
}

// round 7
// speedup vs baseline: 1.4994x; 1.4994x over previous
#include <cuda_runtime.h>
#include <cstdint>
#include <cstddef>

#define NN 100000
#define NE 600000
#define H 128
#define FIN 39

#define BM 128
#define BN 128
#define BK 32

// ---------------- scratch (device globals; no allocation allowed) ----------------
__device__ float g_h[(size_t)NN * H];        // node features          [N,128]
__device__ float g_PQ[(size_t)NN * 4 * H];   // P_a|Q_a|P_e|Q_e        [N,512]
__device__ float g_S[(size_t)NN * 2 * H];    // S_ally | S_enc         [N,256]
__device__ float g_deg[2 * NN];              // deg_ally, deg_enc (as float)

__device__ __forceinline__ void cp16(uint32_t dst, const float* src) {
    asm volatile("cp.async.cg.shared.global [%0], [%1], 16;" :: "r"(dst), "l"(src));
}
__device__ __forceinline__ void ffma2(unsigned long long& d, unsigned long long a,
                                      unsigned long long b) {
    asm("fma.rn.f32x2 %0, %1, %2, %0;" : "+l"(d) : "l"(a), "l"(b));
}
__device__ __forceinline__ unsigned long long pack2(float x) {
    unsigned long long r;
    asm("mov.b64 %0, {%1, %1};" : "=l"(r) : "f"(x));
    return r;
}
__device__ __forceinline__ void unpack2(unsigned long long v, float& lo, float& hi) {
    asm("mov.b64 {%0, %1}, %2;" : "=f"(lo), "=f"(hi) : "l"(v));
}

// ---------------- utility kernels ----------------
__global__ void fill_zero(float4* __restrict__ p, int n4) {
    int i = blockIdx.x * blockDim.x + threadIdx.x;
    int stride = gridDim.x * blockDim.x;
    float4 z = make_float4(0.f, 0.f, 0.f, 0.f);
    for (; i < n4; i += stride) p[i] = z;
}

__global__ void deg_kernel(const int* __restrict__ eia, const int* __restrict__ eie,
                           float* __restrict__ deg) {
    int t = blockIdx.x * blockDim.x + threadIdx.x;
    if (t < NE) {
        atomicAdd(&deg[eia[NE + t]], 1.f);
    } else if (t < 2 * NE) {
        atomicAdd(&deg[NN + eie[NE + (t - NE)]], 1.f);
    }
}

// ---------------- input projection: h = relu(x @ W_in + b_in) ----------------
#define IPN 16
__global__ void __launch_bounds__(128) input_proj(const float* __restrict__ x,
                                                  const float* __restrict__ Win,
                                                  const float* __restrict__ bin,
                                                  float* __restrict__ h) {
    __shared__ float Ws[FIN * H];
    __shared__ float xs[IPN][FIN + 1];
    int tid = threadIdx.x;
    for (int i = tid; i < FIN * H; i += 128) Ws[i] = Win[i];
    int n0 = blockIdx.x * IPN;
    for (int i = tid; i < IPN * FIN; i += 128) {
        int r = i / FIN, c = i - r * FIN;
        xs[r][c] = x[(size_t)(n0 + r) * FIN + c];
    }
    __syncthreads();
    float acc[IPN];
    float bv = bin[tid];
#pragma unroll
    for (int r = 0; r < IPN; r++) acc[r] = bv;
    for (int k = 0; k < FIN; k++) {
        float wv = Ws[k * H + tid];
#pragma unroll
        for (int r = 0; r < IPN; r++) acc[r] = fmaf(xs[r][k], wv, acc[r]);
    }
#pragma unroll
    for (int r = 0; r < IPN; r++)
        h[(size_t)(n0 + r) * H + tid] = fmaxf(acc[r], 0.f);
}

// ---------------- edge phase (both edge sets in one launch; R4-proven) ----------------
__global__ void __launch_bounds__(256) edge_kernel(
    const int* __restrict__ eia, const float* __restrict__ eaa,
    const int* __restrict__ eie, const float* __restrict__ eae,
    const float* __restrict__ PQ,
    const float* __restrict__ w1ca, const float* __restrict__ w1ce,
    float* __restrict__ S) {
    __shared__ __align__(16) float w[512];
    w[threadIdx.x] = w1ca[threadIdx.x];
    w[256 + threadIdx.x] = w1ce[threadIdx.x];
    __syncthreads();
    unsigned gw = blockIdx.x * 8u + (threadIdx.x >> 5);
    int lane = threadIdx.x & 31;
    const int* ei;
    const float* ea;
    int pq_off, s_off, woff, e;
    if (gw < NE) {
        e = gw; ei = eia; ea = eaa; pq_off = 0; s_off = 0; woff = 0;
    } else {
        e = gw - NE; ei = eie; ea = eae; pq_off = 256; s_off = 128; woff = 256;
    }
    int src = ei[e];
    int tgt = ei[NE + e];
    float e0 = ea[2 * e], e1 = ea[2 * e + 1];
    float4 p = *(const float4*)&PQ[(size_t)tgt * 512 + pq_off + lane * 4];
    float4 q = *(const float4*)&PQ[(size_t)src * 512 + pq_off + 128 + lane * 4];
    float4 w0 = *(const float4*)&w[woff + lane * 4];
    float4 w1 = *(const float4*)&w[woff + H + lane * 4];
    float4 t;
    t.x = fmaxf(fmaf(e0, w0.x, fmaf(e1, w1.x, p.x + q.x)), 0.f);
    t.y = fmaxf(fmaf(e0, w0.y, fmaf(e1, w1.y, p.y + q.y)), 0.f);
    t.z = fmaxf(fmaf(e0, w0.z, fmaf(e1, w1.z, p.z + q.z)), 0.f);
    t.w = fmaxf(fmaf(e0, w0.w, fmaf(e1, w1.w, p.w + q.w)), 0.f);
    float* dst = &S[(size_t)tgt * 256 + s_off + lane * 4];
    asm volatile("red.global.add.v4.f32 [%0], {%1,%2,%3,%4};"
                 :: "l"(dst), "f"(t.x), "f"(t.y), "f"(t.z), "f"(t.w) : "memory");
}

// ---------------- fused PQ GEMM: A staged ONCE, 4 weight matrices, 4 outputs ----------------
// out[:, y*128:(y+1)*128] = A @ B[y] (+bias for y==0,2); also zeroes S rows.
// A full-K in smem [128][132]; B double-buffered via cp.async; R4 FFMA2 micro-kernel.
__global__ void __launch_bounds__(128, 2) gemm0_fused(
    const float* __restrict__ A,
    const float* __restrict__ B0, const float* __restrict__ B1,
    const float* __restrict__ B2, const float* __restrict__ B3,
    const float* __restrict__ bias_a, const float* __restrict__ bias_e,
    float* __restrict__ PQ, float* __restrict__ S) {
    extern __shared__ float sm[];
    float(*As)[BM + 4] = (float(*)[BM + 4])sm;                       // [128][132]
    float(*Bs)[BK][BN] = (float(*)[BK][BN])(sm + 128 * (BM + 4));    // [2][32][128]

    int tid = threadIdx.x;
    int tx = tid & 15;
    int ty = tid >> 4;
    int row0 = blockIdx.x * BM;

    int bk0 = tid >> 4;
    int bc = (tid & 15) * 8;
    uint32_t bs_base = (uint32_t)__cvta_generic_to_shared(&Bs[0][0][0]);

    // prologue: B(y=0, kb=0) -> buf0
#pragma unroll
    for (int i = 0; i < 4; i++) {
        int k = bk0 + i * 8;
        const float* s = B0 + (size_t)k * H + bc;
        uint32_t d = bs_base + (unsigned)(k * BN + bc) * 4u;
        cp16(d, s);
        cp16(d + 16, s + 4);
    }
    asm volatile("cp.async.commit_group;" ::: "memory");

    const float4 z4 = make_float4(0.f, 0.f, 0.f, 0.f);
    // zero this block's S rows (overlaps with B prologue in flight)
#pragma unroll
    for (int r = 0; r < 16; r++) {
        int gr = row0 + ty * 16 + r;
        if (gr < NN) {
            float4* dst = (float4*)&S[(size_t)gr * 256 + tx * 16];
            dst[0] = z4; dst[1] = z4; dst[2] = z4; dst[3] = z4;
        }
    }

    // stage full-K A (transposed): one row per thread, 32 float4
    {
        int agr = row0 + tid;
        bool aval = agr < NN;
        const float* Aptr = A + (size_t)(aval ? agr : 0) * H;
#pragma unroll
        for (int j = 0; j < 32; j++) {
            float4 v = aval ? *(const float4*)(Aptr + j * 4) : z4;
            As[j * 4 + 0][tid] = v.x;
            As[j * 4 + 1][tid] = v.y;
            As[j * 4 + 2][tid] = v.z;
            As[j * 4 + 3][tid] = v.w;
        }
    }
    asm volatile("cp.async.wait_group 0;" ::: "memory");
    __syncthreads();

    int col0 = tx * 8;
    for (int y = 0; y < 4; y++) {
        const float* Bp = (y == 0) ? B0 : (y == 1) ? B1 : (y == 2) ? B2 : B3;
        unsigned long long acc[8][8];
#pragma unroll
        for (int rp = 0; rp < 8; rp++)
#pragma unroll
            for (int c = 0; c < 8; c++) acc[rp][c] = 0ull;

        for (int it = 0; it < 4; it++) {
            int t = y * 4 + it;
            int buf = t & 1;
            // issue next B tile into the other buffer
            if (t + 1 < 16) {
                int yn = (t + 1) >> 2;
                int kbn = ((t + 1) & 3) * BK;
                const float* Bn = (yn == 0) ? B0 : (yn == 1) ? B1 : (yn == 2) ? B2 : B3;
                uint32_t bb = bs_base + (unsigned)((buf ^ 1) * BK * BN) * 4u;
#pragma unroll
                for (int i = 0; i < 4; i++) {
                    int k = bk0 + i * 8;
                    const float* s = Bn + (size_t)(kbn + k) * H + bc;
                    uint32_t d = bb + (unsigned)(k * BN + bc) * 4u;
                    cp16(d, s);
                    cp16(d + 16, s + 4);
                }
                asm volatile("cp.async.commit_group;" ::: "memory");
            }
            // compute on buf, k rows it*32..it*32+31 of As
            int kbase = it * BK;
#pragma unroll 4
            for (int k = 0; k < BK; k++) {
                unsigned long long a2[8];
                const ulonglong2* arow = (const ulonglong2*)&As[kbase + k][ty * 16];
#pragma unroll
                for (int j = 0; j < 4; j++) {
                    ulonglong2 v = arow[j];
                    a2[j * 2] = v.x;
                    a2[j * 2 + 1] = v.y;
                }
                float b[8];
                *(float4*)&b[0] = *(const float4*)&Bs[buf][k][tx * 8];
                *(float4*)&b[4] = *(const float4*)&Bs[buf][k][tx * 8 + 4];
                unsigned long long bp[8];
#pragma unroll
                for (int c = 0; c < 8; c++) bp[c] = pack2(b[c]);
#pragma unroll
                for (int rp = 0; rp < 8; rp++)
#pragma unroll
                    for (int c = 0; c < 8; c++) ffma2(acc[rp][c], a2[rp], bp[c]);
            }
            if (t + 1 < 16) {
                asm volatile("cp.async.wait_group 0;" ::: "memory");
                __syncthreads();
            }
        }

        // epilogue for this y
        const float* bias = (y == 0) ? bias_a : (y == 2) ? bias_e : nullptr;
        float bv[8];
#pragma unroll
        for (int c = 0; c < 8; c++) bv[c] = bias ? bias[col0 + c] : 0.f;
        int ocol = y * BN;
#pragma unroll
        for (int rp = 0; rp < 8; rp++) {
            float vlo[8], vhi[8];
#pragma unroll
            for (int c = 0; c < 8; c++) unpack2(acc[rp][c], vlo[c], vhi[c]);
            int gr0 = row0 + ty * 16 + rp * 2;
#pragma unroll
            for (int h2 = 0; h2 < 2; h2++) {
                int gr = gr0 + h2;
                const float* v = h2 ? vhi : vlo;
                if (gr < NN) {
                    float o[8];
#pragma unroll
                    for (int c = 0; c < 8; c++) o[c] = v[c] + bv[c];
                    *(float4*)&PQ[(size_t)gr * 512 + ocol + col0] = *(float4*)o;
                    *(float4*)&PQ[(size_t)gr * 512 + ocol + col0 + 4] = *(float4*)(o + 4);
                }
            }
        }
    }
}

// ---------------- SIMT FFMA2 GEMM (MODE 1: combine+LN, MODE 2: comb MLP) — R4-proven -------
template <int MODE>
__global__ void __launch_bounds__(128, 2) gemm_kernel(
    const float* __restrict__ A, int lda, int Ktot,
    const float* __restrict__ B0, const float* __restrict__ B1,
    const float* __restrict__ bias0,
    const float* __restrict__ resid,
    const float* __restrict__ dega, const float* __restrict__ dege,
    const float* __restrict__ b2a, const float* __restrict__ b2e,
    const float* __restrict__ lng, const float* __restrict__ lnb,
    float* __restrict__ out, int ldo) {
    extern __shared__ float sm[];
    float(*As)[BK][BM + 4] = (float(*)[BK][BM + 4])sm;
    float(*Bs)[BK][BN] = (float(*)[BK][BN])(sm + 2 * BK * (BM + 4));

    int tid = threadIdx.x;
    int tx = tid & 15;
    int ty = tid >> 4;
    int row0 = blockIdx.x * BM;

    const float* B = B0;

    int agr = row0 + tid;
    bool aval = agr < NN;
    const float* Aptr = A + (size_t)(aval ? agr : 0) * lda;
    int bk0 = tid >> 4;
    int bc = (tid & 15) * 8;

    uint32_t bs_base = (uint32_t)__cvta_generic_to_shared(&Bs[0][0][0]);

#pragma unroll
    for (int i = 0; i < 4; i++) {
        int k = bk0 + i * 8;
        const float* s = B + (size_t)k * H + bc;
        uint32_t d = bs_base + (unsigned)(k * BN + bc) * 4u;
        cp16(d, s);
        cp16(d + 16, s + 4);
    }
    asm volatile("cp.async.commit_group;" ::: "memory");

    float4 pa[8];
#pragma unroll
    for (int j = 0; j < 8; j++) pa[j] = *(const float4*)(Aptr + j * 4);

    unsigned long long acc[8][8];
#pragma unroll
    for (int rp = 0; rp < 8; rp++)
#pragma unroll
        for (int c = 0; c < 8; c++) acc[rp][c] = 0ull;

    const int niter = Ktot / BK;
    for (int it = 0; it < niter; it++) {
        int buf = it & 1;
        asm volatile("cp.async.wait_group 0;" ::: "memory");
#pragma unroll
        for (int j = 0; j < 8; j++) {
            int k0 = j * 4;
            As[buf][k0 + 0][tid] = pa[j].x;
            As[buf][k0 + 1][tid] = pa[j].y;
            As[buf][k0 + 2][tid] = pa[j].z;
            As[buf][k0 + 3][tid] = pa[j].w;
        }
        if (it + 1 < niter) {
            const float* ap = Aptr + (it + 1) * BK;
#pragma unroll
            for (int j = 0; j < 8; j++) pa[j] = *(const float4*)(ap + j * 4);
        }
        __syncthreads();
        if (it + 1 < niter) {
            int kb2 = (it + 1) * BK;
            const float* Bp = B;
            int kk = kb2;
            if (MODE == 1 && kb2 >= H) { Bp = B1; kk = kb2 - H; }
            uint32_t bb = bs_base + (unsigned)((buf ^ 1) * BK * BN) * 4u;
#pragma unroll
            for (int i = 0; i < 4; i++) {
                int k = bk0 + i * 8;
                const float* s = Bp + (size_t)(kk + k) * H + bc;
                uint32_t d = bb + (unsigned)(k * BN + bc) * 4u;
                cp16(d, s);
                cp16(d + 16, s + 4);
            }
            asm volatile("cp.async.commit_group;" ::: "memory");
        }
#pragma unroll 4
        for (int k = 0; k < BK; k++) {
            unsigned long long a2[8];
            const ulonglong2* arow = (const ulonglong2*)&As[buf][k][ty * 16];
#pragma unroll
            for (int j = 0; j < 4; j++) {
                ulonglong2 v = arow[j];
                a2[j * 2] = v.x;
                a2[j * 2 + 1] = v.y;
            }
            float b[8];
            *(float4*)&b[0] = *(const float4*)&Bs[buf][k][tx * 8];
            *(float4*)&b[4] = *(const float4*)&Bs[buf][k][tx * 8 + 4];
            unsigned long long bp[8];
#pragma unroll
            for (int c = 0; c < 8; c++) bp[c] = pack2(b[c]);
#pragma unroll
            for (int rp = 0; rp < 8; rp++)
#pragma unroll
                for (int c = 0; c < 8; c++) ffma2(acc[rp][c], a2[rp], bp[c]);
        }
    }

    int col0 = tx * 8;
    if (MODE == 2) {
        float bv[8];
#pragma unroll
        for (int c = 0; c < 8; c++) bv[c] = bias0[col0 + c];
#pragma unroll
        for (int rp = 0; rp < 8; rp++) {
            float vlo[8], vhi[8];
#pragma unroll
            for (int c = 0; c < 8; c++) unpack2(acc[rp][c], vlo[c], vhi[c]);
            int gr0 = row0 + ty * 16 + rp * 2;
#pragma unroll
            for (int h2 = 0; h2 < 2; h2++) {
                int gr = gr0 + h2;
                const float* v = h2 ? vhi : vlo;
                if (gr < NN) {
                    float o[8];
#pragma unroll
                    for (int c = 0; c < 8; c++) {
                        float t = fmaxf(v[c] + bv[c], 0.f);
                        o[c] = t + resid[(size_t)gr * H + col0 + c];
                    }
                    *(float4*)&out[(size_t)gr * ldo + col0] = *(float4*)o;
                    *(float4*)&out[(size_t)gr * ldo + col0 + 4] = *(float4*)(o + 4);
                }
            }
        }
    } else {
        // MODE 1: residual + deg*b2, LayerNorm via 16-lane shuffle reduction
        float b2av[8], b2ev[8], gv[8], bbv[8];
        *(float4*)&b2av[0] = *(const float4*)&b2a[col0];
        *(float4*)&b2av[4] = *(const float4*)&b2a[col0 + 4];
        *(float4*)&b2ev[0] = *(const float4*)&b2e[col0];
        *(float4*)&b2ev[4] = *(const float4*)&b2e[col0 + 4];
        *(float4*)&gv[0] = *(const float4*)&lng[col0];
        *(float4*)&gv[4] = *(const float4*)&lng[col0 + 4];
        *(float4*)&bbv[0] = *(const float4*)&lnb[col0];
        *(float4*)&bbv[4] = *(const float4*)&lnb[col0 + 4];
#pragma unroll
        for (int rp = 0; rp < 8; rp++) {
            float vlo[8], vhi[8];
#pragma unroll
            for (int c = 0; c < 8; c++) unpack2(acc[rp][c], vlo[c], vhi[c]);
            int gr0 = row0 + ty * 16 + rp * 2;
#pragma unroll
            for (int h2 = 0; h2 < 2; h2++) {
                int gr = gr0 + h2;
                float* vv = h2 ? vhi : vlo;
                bool valid = gr < NN;
                float da = valid ? dega[gr] : 0.f;
                float de = valid ? dege[gr] : 0.f;
                float rs[8];
                if (valid) {
                    *(float4*)&rs[0] = *(const float4*)&resid[(size_t)gr * H + col0];
                    *(float4*)&rs[4] = *(const float4*)&resid[(size_t)gr * H + col0 + 4];
                } else {
#pragma unroll
                    for (int c = 0; c < 8; c++) rs[c] = 0.f;
                }
                float v[8];
                float s = 0.f, s2 = 0.f;
#pragma unroll
                for (int c = 0; c < 8; c++) {
                    v[c] = vv[c] + rs[c] + da * b2av[c] + de * b2ev[c];
                    s += v[c];
                    s2 += v[c] * v[c];
                }
#pragma unroll
                for (int off = 8; off; off >>= 1) {
                    s += __shfl_xor_sync(0xffffffffu, s, off);
                    s2 += __shfl_xor_sync(0xffffffffu, s2, off);
                }
                float mu = s * (1.f / 128.f);
                float var = s2 * (1.f / 128.f) - mu * mu;
                float rstd = rsqrtf(var + 1e-5f);
                if (valid) {
                    float o[8];
#pragma unroll
                    for (int c = 0; c < 8; c++) o[c] = (v[c] - mu) * rstd * gv[c] + bbv[c];
                    *(float4*)&out[(size_t)gr * H + col0] = *(float4*)o;
                    *(float4*)&out[(size_t)gr * H + col0 + 4] = *(float4*)(o + 4);
                }
            }
        }
    }
}

// ---------------- launch ----------------
extern "C" void kernel_launch(void* const* d_in, const int* in_sizes, int n_in,
                              void* d_out, int out_size) {
    (void)in_sizes; (void)n_in; (void)out_size;
    const float* x       = (const float*)d_in[0];
    const int*   ally_ei = (const int*)d_in[1];
    const float* ally_ea = (const float*)d_in[2];
    const int*   enc_ei  = (const int*)d_in[3];
    const float* enc_ea  = (const float*)d_in[4];
    const float* W_in    = (const float*)d_in[5];
    const float* b_in    = (const float*)d_in[6];
    const float* ally_W1 = (const float*)d_in[7];
    const float* ally_b1 = (const float*)d_in[8];
    const float* ally_W2 = (const float*)d_in[9];
    const float* ally_b2 = (const float*)d_in[10];
    const float* enc_W1  = (const float*)d_in[11];
    const float* enc_b1  = (const float*)d_in[12];
    const float* enc_W2  = (const float*)d_in[13];
    const float* enc_b2  = (const float*)d_in[14];
    const float* ln_g    = (const float*)d_in[15];
    const float* ln_b    = (const float*)d_in[16];
    const float* comb_W  = (const float*)d_in[17];
    const float* comb_b  = (const float*)d_in[18];
    float* out = (float*)d_out;

    float *h, *PQ, *S, *deg;
    cudaGetSymbolAddress((void**)&h, g_h);
    cudaGetSymbolAddress((void**)&PQ, g_PQ);
    cudaGetSymbolAddress((void**)&S, g_S);
    cudaGetSymbolAddress((void**)&deg, g_deg);
    float* dega = deg;
    float* dege = deg + NN;

    const int SMEM = (2 * BK * (BM + 4) + 2 * BK * BN) * 4;     // 66560 B
    const int SMEM0 = (128 * (BM + 4) + 2 * BK * BN) * 4;       // 100352 B
    cudaFuncSetAttribute(gemm0_fused, cudaFuncAttributeMaxDynamicSharedMemorySize, SMEM0);
    cudaFuncSetAttribute(gemm_kernel<1>, cudaFuncAttributeMaxDynamicSharedMemorySize, SMEM);
    cudaFuncSetAttribute(gemm_kernel<2>, cudaFuncAttributeMaxDynamicSharedMemorySize, SMEM);

    const int nblk = (NN + BM - 1) / BM;  // 782

    // degree (recomputed every call for determinism)
    fill_zero<<<64, 256>>>((float4*)deg, 2 * NN / 4);
    deg_kernel<<<(2 * NE + 255) / 256, 256>>>(ally_ei, enc_ei, deg);

    // input projection
    input_proj<<<NN / IPN, 128>>>(x, W_in, b_in, h);

    for (int i = 0; i < 2; i++) {
        const float* aW1 = ally_W1 + (size_t)i * 258 * H;
        const float* eW1 = enc_W1 + (size_t)i * 258 * H;

        // P/Q for both edge types (A staged once); also zeroes S
        gemm0_fused<<<nblk, 128, SMEM0>>>(
            h, aW1, aW1 + 128 * H, eW1, eW1 + 128 * H,
            ally_b1 + i * H, enc_b1 + i * H, PQ, S);

        // edge scatter for both edge sets in one launch (2E warps)
        edge_kernel<<<2 * NE / 8, 256>>>(ally_ei, ally_ea, enc_ei, enc_ea,
                                         PQ, aW1 + 256 * H, eW1 + 256 * H, S);

        // combine: h = LN(h + S_a@W2a + dega*b2a + S_e@W2e + dege*b2e)
        gemm_kernel<1><<<nblk, 128, SMEM>>>(
            S, 2 * H, 2 * H,
            ally_W2 + (size_t)i * H * H, enc_W2 + (size_t)i * H * H,
            nullptr,
            h, dega, dege,
            ally_b2 + i * H, enc_b2 + i * H,
            ln_g + i * H, ln_b + i * H,
            h, H);

        // comb MLP: h = h + relu(h @ comb_W + comb_b); last layer writes d_out
        float* dst = (i == 1) ? out : h;
        gemm_kernel<2><<<nblk, 128, SMEM>>>(
            h, H, H,
            comb_W + (size_t)i * H * H, nullptr,
            comb_b + i * H,
            h, nullptr, nullptr, nullptr, nullptr, nullptr, nullptr,
            dst, H);
    }
}

// round 8
// speedup vs baseline: 1.5655x; 1.0441x over previous
#include <cuda_runtime.h>
#include <cstdint>
#include <cstddef>

#define NN 100000
#define NE 600000
#define H 128
#define FIN 39

#define BM 128
#define BN 128
#define BK 32

// ---------------- scratch (device globals; no allocation allowed) ----------------
__device__ float g_h[(size_t)NN * H];        // node features          [N,128]
__device__ float g_PQ[(size_t)NN * 4 * H];   // P_a|Q_a|P_e|Q_e        [N,512]
__device__ float g_S[(size_t)NN * 2 * H];    // S_ally | S_enc         [N,256]
__device__ float g_deg[2 * NN];              // deg_ally, deg_enc (as float)

__device__ __forceinline__ void cp16(uint32_t dst, const float* src) {
    asm volatile("cp.async.cg.shared.global [%0], [%1], 16;" :: "r"(dst), "l"(src));
}
__device__ __forceinline__ void ffma2(unsigned long long& d, unsigned long long a,
                                      unsigned long long b) {
    asm("fma.rn.f32x2 %0, %1, %2, %0;" : "+l"(d) : "l"(a), "l"(b));
}
__device__ __forceinline__ unsigned long long pack2(float x) {
    unsigned long long r;
    asm("mov.b64 %0, {%1, %1};" : "=l"(r) : "f"(x));
    return r;
}
__device__ __forceinline__ void unpack2(unsigned long long v, float& lo, float& hi) {
    asm("mov.b64 {%0, %1}, %2;" : "=f"(lo), "=f"(hi) : "l"(v));
}

// ---------------- utility kernels ----------------
__global__ void fill_zero(float4* __restrict__ p, int n4) {
    int i = blockIdx.x * blockDim.x + threadIdx.x;
    int stride = gridDim.x * blockDim.x;
    float4 z = make_float4(0.f, 0.f, 0.f, 0.f);
    for (; i < n4; i += stride) p[i] = z;
}

__global__ void deg_kernel(const int* __restrict__ eia, const int* __restrict__ eie,
                           float* __restrict__ deg) {
    int t = blockIdx.x * blockDim.x + threadIdx.x;
    if (t < NE) {
        atomicAdd(&deg[eia[NE + t]], 1.f);
    } else if (t < 2 * NE) {
        atomicAdd(&deg[NN + eie[NE + (t - NE)]], 1.f);
    }
}

// ---------------- input projection: h = relu(x @ W_in + b_in) ----------------
// LDS-lean inner loop: per 4 k-steps, 4 scalar Ws LDS + 16 broadcast xs LDS.128.
#define IPN 16
__global__ void __launch_bounds__(128) input_proj(const float* __restrict__ x,
                                                  const float* __restrict__ Win,
                                                  const float* __restrict__ bin,
                                                  float* __restrict__ h) {
    __shared__ float Ws[FIN * H];
    __shared__ __align__(16) float xs[IPN][FIN + 1];  // 40 floats/row, 16B aligned
    int tid = threadIdx.x;
    for (int i = tid; i < FIN * H; i += 128) Ws[i] = Win[i];
    int n0 = blockIdx.x * IPN;  // N divisible by 16
    for (int i = tid; i < IPN * FIN; i += 128) {
        int r = i / FIN, c = i - r * FIN;
        xs[r][c] = x[(size_t)(n0 + r) * FIN + c];
    }
    __syncthreads();
    float acc[IPN];
    float bv = bin[tid];
#pragma unroll
    for (int r = 0; r < IPN; r++) acc[r] = bv;
    // 9 groups of 4 k-steps
#pragma unroll
    for (int k4 = 0; k4 < 9; k4++) {
        float wv0 = Ws[(k4 * 4 + 0) * H + tid];
        float wv1 = Ws[(k4 * 4 + 1) * H + tid];
        float wv2 = Ws[(k4 * 4 + 2) * H + tid];
        float wv3 = Ws[(k4 * 4 + 3) * H + tid];
#pragma unroll
        for (int r = 0; r < IPN; r++) {
            float4 xv = *(const float4*)&xs[r][k4 * 4];
            acc[r] = fmaf(xv.x, wv0, acc[r]);
            acc[r] = fmaf(xv.y, wv1, acc[r]);
            acc[r] = fmaf(xv.z, wv2, acc[r]);
            acc[r] = fmaf(xv.w, wv3, acc[r]);
        }
    }
    // tail k = 36..38
#pragma unroll
    for (int k = 36; k < FIN; k++) {
        float wv = Ws[k * H + tid];
#pragma unroll
        for (int r = 0; r < IPN; r++) acc[r] = fmaf(xs[r][k], wv, acc[r]);
    }
#pragma unroll
    for (int r = 0; r < IPN; r++)
        h[(size_t)(n0 + r) * H + tid] = fmaxf(acc[r], 0.f);
}

// ---------------- edge phase (both edge sets in one launch) ----------------
// warp per edge: S[tgt] += relu(P[tgt] + Q[src] + ea @ W1c)
__global__ void __launch_bounds__(256) edge_kernel(
    const int* __restrict__ eia, const float* __restrict__ eaa,
    const int* __restrict__ eie, const float* __restrict__ eae,
    const float* __restrict__ PQ,
    const float* __restrict__ w1ca, const float* __restrict__ w1ce,
    float* __restrict__ S) {
    __shared__ __align__(16) float w[512];
    w[threadIdx.x] = w1ca[threadIdx.x];
    w[256 + threadIdx.x] = w1ce[threadIdx.x];
    __syncthreads();
    unsigned gw = blockIdx.x * 8u + (threadIdx.x >> 5);
    int lane = threadIdx.x & 31;
    const int* ei;
    const float* ea;
    int pq_off, s_off, woff, e;
    if (gw < NE) {
        e = gw; ei = eia; ea = eaa; pq_off = 0; s_off = 0; woff = 0;
    } else {
        e = gw - NE; ei = eie; ea = eae; pq_off = 256; s_off = 128; woff = 256;
    }
    int src = ei[e];
    int tgt = ei[NE + e];
    float e0 = ea[2 * e], e1 = ea[2 * e + 1];
    float4 p = *(const float4*)&PQ[(size_t)tgt * 512 + pq_off + lane * 4];
    float4 q = *(const float4*)&PQ[(size_t)src * 512 + pq_off + 128 + lane * 4];
    float4 w0 = *(const float4*)&w[woff + lane * 4];
    float4 w1 = *(const float4*)&w[woff + H + lane * 4];
    float4 t;
    t.x = fmaxf(fmaf(e0, w0.x, fmaf(e1, w1.x, p.x + q.x)), 0.f);
    t.y = fmaxf(fmaf(e0, w0.y, fmaf(e1, w1.y, p.y + q.y)), 0.f);
    t.z = fmaxf(fmaf(e0, w0.z, fmaf(e1, w1.z, p.z + q.z)), 0.f);
    t.w = fmaxf(fmaf(e0, w0.w, fmaf(e1, w1.w, p.w + q.w)), 0.f);
    float* dst = &S[(size_t)tgt * 256 + s_off + lane * 4];
    asm volatile("red.global.add.v4.f32 [%0], {%1,%2,%3,%4};"
                 :: "l"(dst), "f"(t.x), "f"(t.y), "f"(t.z), "f"(t.w) : "memory");
}

// ---------------- 128x128 SGEMM, 128 threads, 16x8 micro-tile, FFMA2 (R4-proven) ------------
// MODE 0 (PQ):      out[:, y*128:(y+1)*128] = h @ B[y] (+bias y==0,2); y==0 zeroes S
// MODE 1 (COMBINE): u = S@[W2a;W2e] + h + dega*b2a + dege*b2e; h = LayerNorm(u)
// MODE 2 (COMB):    out = resid + relu(h @ B0 + bias0)
template <int MODE>
__global__ void __launch_bounds__(128, 2) gemm_kernel(
    const float* __restrict__ A, int lda, int Ktot,
    const float* __restrict__ B0, const float* __restrict__ B1,
    const float* __restrict__ B2, const float* __restrict__ B3,
    const float* __restrict__ bias0, const float* __restrict__ bias2,
    const float* __restrict__ resid,
    const float* __restrict__ dega, const float* __restrict__ dege,
    const float* __restrict__ b2a, const float* __restrict__ b2e,
    const float* __restrict__ lng, const float* __restrict__ lnb,
    float* __restrict__ out, int ldo,
    float* __restrict__ Szero) {
    extern __shared__ float sm[];
    float(*As)[BK][BM + 4] = (float(*)[BK][BM + 4])sm;                  // [2][32][132]
    float(*Bs)[BK][BN] = (float(*)[BK][BN])(sm + 2 * BK * (BM + 4));    // [2][32][128]

    int tid = threadIdx.x;
    int tx = tid & 15;   // col group (8 cols)
    int ty = tid >> 4;   // row group (16 rows)
    int row0 = blockIdx.x * BM;

    const float* B = B0;
    const float* bias = bias0;
    int ocol = 0;
    if (MODE == 0) {
        int y = blockIdx.y;
        B = (y == 0) ? B0 : (y == 1) ? B1 : (y == 2) ? B2 : B3;
        bias = (y == 0) ? bias0 : (y == 2) ? bias2 : nullptr;
        ocol = y * BN;
    }

    // A staging: one row per thread (32 floats = 8 float4), transposed store
    int agr = row0 + tid;
    bool aval = agr < NN;
    const float* Aptr = A + (size_t)(aval ? agr : 0) * lda;
    // B staging: per thread 4 k-rows (bk0+8i), 2 float4 each (8 cp.async)
    int bk0 = tid >> 4;        // 0..7
    int bc = (tid & 15) * 8;   // 0..120

    uint32_t bs_base = (uint32_t)__cvta_generic_to_shared(&Bs[0][0][0]);

    // prologue: B(0) -> buf0, A(0) -> regs
#pragma unroll
    for (int i = 0; i < 4; i++) {
        int k = bk0 + i * 8;
        const float* s = B + (size_t)k * H + bc;
        uint32_t d = bs_base + (unsigned)(k * BN + bc) * 4u;
        cp16(d, s);
        cp16(d + 16, s + 4);
    }
    asm volatile("cp.async.commit_group;" ::: "memory");

    float4 pa[8];
#pragma unroll
    for (int j = 0; j < 8; j++) pa[j] = *(const float4*)(Aptr + j * 4);

    unsigned long long acc[8][8];  // row-pair x col, packed f32x2
#pragma unroll
    for (int rp = 0; rp < 8; rp++)
#pragma unroll
        for (int c = 0; c < 8; c++) acc[rp][c] = 0ull;

    const int niter = Ktot / BK;
    for (int it = 0; it < niter; it++) {
        int buf = it & 1;
        asm volatile("cp.async.wait_group 0;" ::: "memory");
        // commit A regs -> As[buf] (transposed)
#pragma unroll
        for (int j = 0; j < 8; j++) {
            int k0 = j * 4;
            As[buf][k0 + 0][tid] = pa[j].x;
            As[buf][k0 + 1][tid] = pa[j].y;
            As[buf][k0 + 2][tid] = pa[j].z;
            As[buf][k0 + 3][tid] = pa[j].w;
        }
        // prefetch next A into regs
        if (it + 1 < niter) {
            const float* ap = Aptr + (it + 1) * BK;
#pragma unroll
            for (int j = 0; j < 8; j++) pa[j] = *(const float4*)(ap + j * 4);
        }
        __syncthreads();
        // issue next B tile into the other buffer
        if (it + 1 < niter) {
            int kb2 = (it + 1) * BK;
            const float* Bp = B;
            int kk = kb2;
            if (MODE == 1 && kb2 >= H) { Bp = B1; kk = kb2 - H; }
            uint32_t bb = bs_base + (unsigned)((buf ^ 1) * BK * BN) * 4u;
#pragma unroll
            for (int i = 0; i < 4; i++) {
                int k = bk0 + i * 8;
                const float* s = Bp + (size_t)(kk + k) * H + bc;
                uint32_t d = bb + (unsigned)(k * BN + bc) * 4u;
                cp16(d, s);
                cp16(d + 16, s + 4);
            }
            asm volatile("cp.async.commit_group;" ::: "memory");
        }
        // compute: FFMA2, rows packed in pairs
#pragma unroll 4
        for (int k = 0; k < BK; k++) {
            unsigned long long a2[8];
            const ulonglong2* arow = (const ulonglong2*)&As[buf][k][ty * 16];
#pragma unroll
            for (int j = 0; j < 4; j++) {
                ulonglong2 v = arow[j];
                a2[j * 2] = v.x;
                a2[j * 2 + 1] = v.y;
            }
            float b[8];
            *(float4*)&b[0] = *(const float4*)&Bs[buf][k][tx * 8];
            *(float4*)&b[4] = *(const float4*)&Bs[buf][k][tx * 8 + 4];
            unsigned long long bp[8];
#pragma unroll
            for (int c = 0; c < 8; c++) bp[c] = pack2(b[c]);
#pragma unroll
            for (int rp = 0; rp < 8; rp++)
#pragma unroll
                for (int c = 0; c < 8; c++) ffma2(acc[rp][c], a2[rp], bp[c]);
        }
    }

    int col0 = tx * 8;
    const float4 z4 = make_float4(0.f, 0.f, 0.f, 0.f);

    if (MODE == 0) {
        float bv[8];
#pragma unroll
        for (int c = 0; c < 8; c++) bv[c] = bias ? bias[col0 + c] : 0.f;
#pragma unroll
        for (int rp = 0; rp < 8; rp++) {
            float vlo[8], vhi[8];
#pragma unroll
            for (int c = 0; c < 8; c++) unpack2(acc[rp][c], vlo[c], vhi[c]);
            int gr0 = row0 + ty * 16 + rp * 2;
#pragma unroll
            for (int h2 = 0; h2 < 2; h2++) {
                int gr = gr0 + h2;
                const float* v = h2 ? vhi : vlo;
                if (gr < NN) {
                    float o[8];
#pragma unroll
                    for (int c = 0; c < 8; c++) o[c] = v[c] + bv[c];
                    *(float4*)&out[(size_t)gr * ldo + ocol + col0] = *(float4*)o;
                    *(float4*)&out[(size_t)gr * ldo + ocol + col0 + 4] = *(float4*)(o + 4);
                }
            }
        }
        if (blockIdx.y == 0 && Szero) {
#pragma unroll
            for (int r = 0; r < 16; r++) {
                int gr = row0 + ty * 16 + r;
                if (gr < NN) {
                    float4* dst = (float4*)&Szero[(size_t)gr * 256 + tx * 16];
                    dst[0] = z4; dst[1] = z4; dst[2] = z4; dst[3] = z4;
                }
            }
        }
    } else if (MODE == 2) {
        float bv[8];
#pragma unroll
        for (int c = 0; c < 8; c++) bv[c] = bias0[col0 + c];
#pragma unroll
        for (int rp = 0; rp < 8; rp++) {
            float vlo[8], vhi[8];
#pragma unroll
            for (int c = 0; c < 8; c++) unpack2(acc[rp][c], vlo[c], vhi[c]);
            int gr0 = row0 + ty * 16 + rp * 2;
#pragma unroll
            for (int h2 = 0; h2 < 2; h2++) {
                int gr = gr0 + h2;
                const float* v = h2 ? vhi : vlo;
                if (gr < NN) {
                    float o[8];
#pragma unroll
                    for (int c = 0; c < 8; c++) {
                        float t = fmaxf(v[c] + bv[c], 0.f);
                        o[c] = t + resid[(size_t)gr * H + col0 + c];
                    }
                    *(float4*)&out[(size_t)gr * ldo + col0] = *(float4*)o;
                    *(float4*)&out[(size_t)gr * ldo + col0 + 4] = *(float4*)(o + 4);
                }
            }
        }
    } else {
        // MODE 1: residual + deg*b2, LayerNorm via 16-lane shuffle reduction
        float b2av[8], b2ev[8], gv[8], bbv[8];
        *(float4*)&b2av[0] = *(const float4*)&b2a[col0];
        *(float4*)&b2av[4] = *(const float4*)&b2a[col0 + 4];
        *(float4*)&b2ev[0] = *(const float4*)&b2e[col0];
        *(float4*)&b2ev[4] = *(const float4*)&b2e[col0 + 4];
        *(float4*)&gv[0] = *(const float4*)&lng[col0];
        *(float4*)&gv[4] = *(const float4*)&lng[col0 + 4];
        *(float4*)&bbv[0] = *(const float4*)&lnb[col0];
        *(float4*)&bbv[4] = *(const float4*)&lnb[col0 + 4];
#pragma unroll
        for (int rp = 0; rp < 8; rp++) {
            float vlo[8], vhi[8];
#pragma unroll
            for (int c = 0; c < 8; c++) unpack2(acc[rp][c], vlo[c], vhi[c]);
            int gr0 = row0 + ty * 16 + rp * 2;
#pragma unroll
            for (int h2 = 0; h2 < 2; h2++) {
                int gr = gr0 + h2;
                float* vv = h2 ? vhi : vlo;
                bool valid = gr < NN;
                float da = valid ? dega[gr] : 0.f;
                float de = valid ? dege[gr] : 0.f;
                float rs[8];
                if (valid) {
                    *(float4*)&rs[0] = *(const float4*)&resid[(size_t)gr * H + col0];
                    *(float4*)&rs[4] = *(const float4*)&resid[(size_t)gr * H + col0 + 4];
                } else {
#pragma unroll
                    for (int c = 0; c < 8; c++) rs[c] = 0.f;
                }
                float v[8];
                float s = 0.f, s2 = 0.f;
#pragma unroll
                for (int c = 0; c < 8; c++) {
                    v[c] = vv[c] + rs[c] + da * b2av[c] + de * b2ev[c];
                    s += v[c];
                    s2 += v[c] * v[c];
                }
#pragma unroll
                for (int off = 8; off; off >>= 1) {
                    s += __shfl_xor_sync(0xffffffffu, s, off);
                    s2 += __shfl_xor_sync(0xffffffffu, s2, off);
                }
                float mu = s * (1.f / 128.f);
                float var = s2 * (1.f / 128.f) - mu * mu;
                float rstd = rsqrtf(var + 1e-5f);
                if (valid) {
                    float o[8];
#pragma unroll
                    for (int c = 0; c < 8; c++) o[c] = (v[c] - mu) * rstd * gv[c] + bbv[c];
                    *(float4*)&out[(size_t)gr * H + col0] = *(float4*)o;
                    *(float4*)&out[(size_t)gr * H + col0 + 4] = *(float4*)(o + 4);
                }
            }
        }
    }
}

// ---------------- launch ----------------
extern "C" void kernel_launch(void* const* d_in, const int* in_sizes, int n_in,
                              void* d_out, int out_size) {
    (void)in_sizes; (void)n_in; (void)out_size;
    const float* x       = (const float*)d_in[0];
    const int*   ally_ei = (const int*)d_in[1];
    const float* ally_ea = (const float*)d_in[2];
    const int*   enc_ei  = (const int*)d_in[3];
    const float* enc_ea  = (const float*)d_in[4];
    const float* W_in    = (const float*)d_in[5];
    const float* b_in    = (const float*)d_in[6];
    const float* ally_W1 = (const float*)d_in[7];
    const float* ally_b1 = (const float*)d_in[8];
    const float* ally_W2 = (const float*)d_in[9];
    const float* ally_b2 = (const float*)d_in[10];
    const float* enc_W1  = (const float*)d_in[11];
    const float* enc_b1  = (const float*)d_in[12];
    const float* enc_W2  = (const float*)d_in[13];
    const float* enc_b2  = (const float*)d_in[14];
    const float* ln_g    = (const float*)d_in[15];
    const float* ln_b    = (const float*)d_in[16];
    const float* comb_W  = (const float*)d_in[17];
    const float* comb_b  = (const float*)d_in[18];
    float* out = (float*)d_out;

    float *h, *PQ, *S, *deg;
    cudaGetSymbolAddress((void**)&h, g_h);
    cudaGetSymbolAddress((void**)&PQ, g_PQ);
    cudaGetSymbolAddress((void**)&S, g_S);
    cudaGetSymbolAddress((void**)&deg, g_deg);
    float* dega = deg;
    float* dege = deg + NN;

    const int SMEM = (2 * BK * (BM + 4) + 2 * BK * BN) * 4;  // 66560 B
    cudaFuncSetAttribute(gemm_kernel<0>, cudaFuncAttributeMaxDynamicSharedMemorySize, SMEM);
    cudaFuncSetAttribute(gemm_kernel<1>, cudaFuncAttributeMaxDynamicSharedMemorySize, SMEM);
    cudaFuncSetAttribute(gemm_kernel<2>, cudaFuncAttributeMaxDynamicSharedMemorySize, SMEM);

    const int nblk = (NN + BM - 1) / BM;  // 782

    // degree (recomputed every call for determinism)
    fill_zero<<<64, 256>>>((float4*)deg, 2 * NN / 4);
    deg_kernel<<<(2 * NE + 255) / 256, 256>>>(ally_ei, enc_ei, deg);

    // input projection
    input_proj<<<NN / IPN, 128>>>(x, W_in, b_in, h);

    for (int i = 0; i < 2; i++) {
        const float* aW1 = ally_W1 + (size_t)i * 258 * H;
        const float* eW1 = enc_W1 + (size_t)i * 258 * H;

        // P/Q for both edge types; y==0 blocks additionally zero S
        gemm_kernel<0><<<dim3(nblk, 4), 128, SMEM>>>(
            h, H, H,
            aW1, aW1 + 128 * H, eW1, eW1 + 128 * H,
            ally_b1 + i * H, enc_b1 + i * H,
            nullptr, nullptr, nullptr, nullptr, nullptr, nullptr, nullptr,
            PQ, 4 * H, S);

        // edge scatter for both edge sets in one launch (2E warps)
        edge_kernel<<<2 * NE / 8, 256>>>(ally_ei, ally_ea, enc_ei, enc_ea,
                                         PQ, aW1 + 256 * H, eW1 + 256 * H, S);

        // combine: h = LN(h + S_a@W2a + dega*b2a + S_e@W2e + dege*b2e)
        gemm_kernel<1><<<nblk, 128, SMEM>>>(
            S, 2 * H, 2 * H,
            ally_W2 + (size_t)i * H * H, enc_W2 + (size_t)i * H * H,
            nullptr, nullptr, nullptr, nullptr,
            h, dega, dege,
            ally_b2 + i * H, enc_b2 + i * H,
            ln_g + i * H, ln_b + i * H,
            h, H, nullptr);

        // comb MLP: h = h + relu(h @ comb_W + comb_b); last layer writes d_out
        float* dst = (i == 1) ? out : h;
        gemm_kernel<2><<<nblk, 128, SMEM>>>(
            h, H, H,
            comb_W + (size_t)i * H * H, nullptr, nullptr, nullptr,
            comb_b + i * H, nullptr,
            h, nullptr, nullptr, nullptr, nullptr, nullptr, nullptr,
            dst, H, nullptr);
    }
}

// round 9
// speedup vs baseline: 1.8338x; 1.1714x over previous
#include <cuda_runtime.h>
#include <cstdint>
#include <cstddef>

#define NN 100000
#define NE 600000
#define H 128
#define FIN 39

#define BM 128
#define BN 128
#define BK 32

#define N2 (2 * NN)                    // 200000 (ally nodes | enc nodes)
#define SCB 512
#define NB1 ((N2 + SCB - 1) / SCB)     // 391

// ---------------- scratch (device globals; no allocation allowed) ----------------
__device__ float g_h[(size_t)NN * H];        // node features          [N,128]
__device__ float g_PQ[(size_t)NN * 4 * H];   // P_a|Q_a|P_e|Q_e        [N,512]
__device__ float g_S[(size_t)NN * 2 * H];    // S_ally | S_enc         [N,256]
__device__ float g_deg[N2];                  // deg_ally | deg_enc (float)
__device__ int g_cnt[N2];                    // per-target edge counts
__device__ int g_rp[N2 + 1];                 // CSR row pointers (global over both sets)
__device__ int g_cur[N2];                    // fill cursors
__device__ int g_bsum[SCB];                  // scan block sums
__device__ __align__(16) float4 g_edges[2 * (size_t)NE];  // {src_bits, e0, e1, pad}

__device__ __forceinline__ void cp16(uint32_t dst, const float* src) {
    asm volatile("cp.async.cg.shared.global [%0], [%1], 16;" :: "r"(dst), "l"(src));
}
__device__ __forceinline__ void ffma2(unsigned long long& d, unsigned long long a,
                                      unsigned long long b) {
    asm("fma.rn.f32x2 %0, %1, %2, %0;" : "+l"(d) : "l"(a), "l"(b));
}
__device__ __forceinline__ unsigned long long pack2(float x) {
    unsigned long long r;
    asm("mov.b64 %0, {%1, %1};" : "=l"(r) : "f"(x));
    return r;
}
__device__ __forceinline__ void unpack2(unsigned long long v, float& lo, float& hi) {
    asm("mov.b64 {%0, %1}, %2;" : "=f"(lo), "=f"(hi) : "l"(v));
}

// ---------------- utility kernels ----------------
__global__ void fill_zero(float4* __restrict__ p, int n4) {
    int i = blockIdx.x * blockDim.x + threadIdx.x;
    int stride = gridDim.x * blockDim.x;
    float4 z = make_float4(0.f, 0.f, 0.f, 0.f);
    for (; i < n4; i += stride) p[i] = z;
}

// ---------------- CSR build ----------------
__global__ void hist_kernel(const int* __restrict__ eia, const int* __restrict__ eie,
                            int* __restrict__ cnt) {
    int t = blockIdx.x * blockDim.x + threadIdx.x;
    if (t < NE) {
        atomicAdd(&cnt[eia[NE + t]], 1);
    } else if (t < 2 * NE) {
        atomicAdd(&cnt[NN + eie[t]], 1);   // eie[NE + (t-NE)]
    }
}

__global__ void scan1(const int* __restrict__ cnt, int* __restrict__ rp,
                      int* __restrict__ bsum) {
    __shared__ int sh[SCB];
    int tid = threadIdx.x;
    int i = blockIdx.x * SCB + tid;
    int v = (i < N2) ? cnt[i] : 0;
    sh[tid] = v;
    __syncthreads();
    for (int off = 1; off < SCB; off <<= 1) {
        int t = (tid >= off) ? sh[tid - off] : 0;
        __syncthreads();
        sh[tid] += t;
        __syncthreads();
    }
    if (i < N2) rp[i] = sh[tid] - v;        // exclusive within block
    if (tid == SCB - 1) bsum[blockIdx.x] = sh[tid];
}

__global__ void scan2(int* __restrict__ bsum) {
    __shared__ int sh[SCB];
    int tid = threadIdx.x;
    int v = (tid < NB1) ? bsum[tid] : 0;
    sh[tid] = v;
    __syncthreads();
    for (int off = 1; off < SCB; off <<= 1) {
        int t = (tid >= off) ? sh[tid - off] : 0;
        __syncthreads();
        sh[tid] += t;
        __syncthreads();
    }
    if (tid < NB1) bsum[tid] = sh[tid] - v;  // exclusive
}

__global__ void scan3(const int* __restrict__ cnt, int* __restrict__ rp,
                      const int* __restrict__ bsum, int* __restrict__ cur,
                      float* __restrict__ deg) {
    int i = blockIdx.x * SCB + threadIdx.x;
    if (i < N2) {
        int e = rp[i] + bsum[blockIdx.x];
        rp[i] = e;
        cur[i] = e;
        deg[i] = (float)cnt[i];
    }
    if (i == 0) rp[N2] = 2 * NE;
}

__global__ void fill_csr(const int* __restrict__ eia, const float* __restrict__ eaa,
                         const int* __restrict__ eie, const float* __restrict__ eae,
                         int* __restrict__ cur, float4* __restrict__ edges) {
    int t = blockIdx.x * blockDim.x + threadIdx.x;
    if (t < NE) {
        int src = eia[t], tgt = eia[NE + t];
        int pos = atomicAdd(&cur[tgt], 1);
        edges[pos] = make_float4(__int_as_float(src), eaa[2 * t], eaa[2 * t + 1], 0.f);
    } else if (t < 2 * NE) {
        int e = t - NE;
        int src = eie[e], tgt = eie[NE + e];
        int pos = atomicAdd(&cur[NN + tgt], 1);
        edges[pos] = make_float4(__int_as_float(src), eae[2 * e], eae[2 * e + 1], 0.f);
    }
}

// ---------------- input projection: h = relu(x @ W_in + b_in) ----------------
#define IPN 16
__global__ void __launch_bounds__(128) input_proj(const float* __restrict__ x,
                                                  const float* __restrict__ Win,
                                                  const float* __restrict__ bin,
                                                  float* __restrict__ h) {
    __shared__ float Ws[FIN * H];
    __shared__ __align__(16) float xs[IPN][FIN + 1];
    int tid = threadIdx.x;
    for (int i = tid; i < FIN * H; i += 128) Ws[i] = Win[i];
    int n0 = blockIdx.x * IPN;
    for (int i = tid; i < IPN * FIN; i += 128) {
        int r = i / FIN, c = i - r * FIN;
        xs[r][c] = x[(size_t)(n0 + r) * FIN + c];
    }
    __syncthreads();
    float acc[IPN];
    float bv = bin[tid];
#pragma unroll
    for (int r = 0; r < IPN; r++) acc[r] = bv;
#pragma unroll
    for (int k4 = 0; k4 < 9; k4++) {
        float wv0 = Ws[(k4 * 4 + 0) * H + tid];
        float wv1 = Ws[(k4 * 4 + 1) * H + tid];
        float wv2 = Ws[(k4 * 4 + 2) * H + tid];
        float wv3 = Ws[(k4 * 4 + 3) * H + tid];
#pragma unroll
        for (int r = 0; r < IPN; r++) {
            float4 xv = *(const float4*)&xs[r][k4 * 4];
            acc[r] = fmaf(xv.x, wv0, acc[r]);
            acc[r] = fmaf(xv.y, wv1, acc[r]);
            acc[r] = fmaf(xv.z, wv2, acc[r]);
            acc[r] = fmaf(xv.w, wv3, acc[r]);
        }
    }
#pragma unroll
    for (int k = 36; k < FIN; k++) {
        float wv = Ws[k * H + tid];
#pragma unroll
        for (int r = 0; r < IPN; r++) acc[r] = fmaf(xs[r][k], wv, acc[r]);
    }
#pragma unroll
    for (int r = 0; r < IPN; r++)
        h[(size_t)(n0 + r) * H + tid] = fmaxf(acc[r], 0.f);
}

// ---------------- CSR edge pass: warp per target node, no atomics ----------------
// S[node] = sum_j relu(P[node] + Q[src_j] + e0_j*w0 + e1_j*w1); degree-0 -> zeros.
__global__ void __launch_bounds__(256) edge_csr(
    const int* __restrict__ rp, const float4* __restrict__ edges,
    const float* __restrict__ PQ,
    const float* __restrict__ w1ca, const float* __restrict__ w1ce,
    float* __restrict__ S) {
    __shared__ __align__(16) float w[512];
    w[threadIdx.x] = w1ca[threadIdx.x];
    w[256 + threadIdx.x] = w1ce[threadIdx.x];
    __syncthreads();
    unsigned gw = blockIdx.x * 8u + (threadIdx.x >> 5);  // grid exactly N2/8 blocks
    int lane = threadIdx.x & 31;
    bool ally = gw < NN;
    int n = ally ? gw : gw - NN;
    size_t prow = (size_t)n * 512 + (ally ? 0 : 256);
    int qcol = ally ? 128 : 384;
    int woff = ally ? 0 : 256;
    int start = rp[gw], end = rp[gw + 1];

    float4 p = *(const float4*)&PQ[prow + lane * 4];
    float4 w0 = *(const float4*)&w[woff + lane * 4];
    float4 w1 = *(const float4*)&w[woff + 128 + lane * 4];
    float4 acc = make_float4(0.f, 0.f, 0.f, 0.f);

    for (int j = start; j < end; j++) {
        float4 er = edges[j];                      // uniform across warp
        int src = __float_as_int(er.x);
        float4 q = *(const float4*)&PQ[(size_t)src * 512 + qcol + lane * 4];
        float e0 = er.y, e1 = er.z;
        acc.x += fmaxf(fmaf(e0, w0.x, fmaf(e1, w1.x, p.x + q.x)), 0.f);
        acc.y += fmaxf(fmaf(e0, w0.y, fmaf(e1, w1.y, p.y + q.y)), 0.f);
        acc.z += fmaxf(fmaf(e0, w0.z, fmaf(e1, w1.z, p.z + q.z)), 0.f);
        acc.w += fmaxf(fmaf(e0, w0.w, fmaf(e1, w1.w, p.w + q.w)), 0.f);
    }
    *(float4*)&S[(size_t)n * 256 + (ally ? 0 : 128) + lane * 4] = acc;
}

// ---------------- 128x128 SGEMM, 128 threads, 16x8 micro-tile, FFMA2 (R4-proven) ------------
// MODE 0 (PQ):      out[:, y*128:(y+1)*128] = h @ B[y] (+bias y==0,2)
// MODE 1 (COMBINE): u = S@[W2a;W2e] + h + dega*b2a + dege*b2e; h = LayerNorm(u)
// MODE 2 (COMB):    out = resid + relu(h @ B0 + bias0)
template <int MODE>
__global__ void __launch_bounds__(128, 2) gemm_kernel(
    const float* __restrict__ A, int lda, int Ktot,
    const float* __restrict__ B0, const float* __restrict__ B1,
    const float* __restrict__ B2, const float* __restrict__ B3,
    const float* __restrict__ bias0, const float* __restrict__ bias2,
    const float* __restrict__ resid,
    const float* __restrict__ dega, const float* __restrict__ dege,
    const float* __restrict__ b2a, const float* __restrict__ b2e,
    const float* __restrict__ lng, const float* __restrict__ lnb,
    float* __restrict__ out, int ldo) {
    extern __shared__ float sm[];
    float(*As)[BK][BM + 4] = (float(*)[BK][BM + 4])sm;                  // [2][32][132]
    float(*Bs)[BK][BN] = (float(*)[BK][BN])(sm + 2 * BK * (BM + 4));    // [2][32][128]

    int tid = threadIdx.x;
    int tx = tid & 15;
    int ty = tid >> 4;
    int row0 = blockIdx.x * BM;

    const float* B = B0;
    const float* bias = bias0;
    int ocol = 0;
    if (MODE == 0) {
        int y = blockIdx.y;
        B = (y == 0) ? B0 : (y == 1) ? B1 : (y == 2) ? B2 : B3;
        bias = (y == 0) ? bias0 : (y == 2) ? bias2 : nullptr;
        ocol = y * BN;
    }

    int agr = row0 + tid;
    bool aval = agr < NN;
    const float* Aptr = A + (size_t)(aval ? agr : 0) * lda;
    int bk0 = tid >> 4;
    int bc = (tid & 15) * 8;

    uint32_t bs_base = (uint32_t)__cvta_generic_to_shared(&Bs[0][0][0]);

#pragma unroll
    for (int i = 0; i < 4; i++) {
        int k = bk0 + i * 8;
        const float* s = B + (size_t)k * H + bc;
        uint32_t d = bs_base + (unsigned)(k * BN + bc) * 4u;
        cp16(d, s);
        cp16(d + 16, s + 4);
    }
    asm volatile("cp.async.commit_group;" ::: "memory");

    float4 pa[8];
#pragma unroll
    for (int j = 0; j < 8; j++) pa[j] = *(const float4*)(Aptr + j * 4);

    unsigned long long acc[8][8];
#pragma unroll
    for (int rp2 = 0; rp2 < 8; rp2++)
#pragma unroll
        for (int c = 0; c < 8; c++) acc[rp2][c] = 0ull;

    const int niter = Ktot / BK;
    for (int it = 0; it < niter; it++) {
        int buf = it & 1;
        asm volatile("cp.async.wait_group 0;" ::: "memory");
#pragma unroll
        for (int j = 0; j < 8; j++) {
            int k0 = j * 4;
            As[buf][k0 + 0][tid] = pa[j].x;
            As[buf][k0 + 1][tid] = pa[j].y;
            As[buf][k0 + 2][tid] = pa[j].z;
            As[buf][k0 + 3][tid] = pa[j].w;
        }
        if (it + 1 < niter) {
            const float* ap = Aptr + (it + 1) * BK;
#pragma unroll
            for (int j = 0; j < 8; j++) pa[j] = *(const float4*)(ap + j * 4);
        }
        __syncthreads();
        if (it + 1 < niter) {
            int kb2 = (it + 1) * BK;
            const float* Bp = B;
            int kk = kb2;
            if (MODE == 1 && kb2 >= H) { Bp = B1; kk = kb2 - H; }
            uint32_t bb = bs_base + (unsigned)((buf ^ 1) * BK * BN) * 4u;
#pragma unroll
            for (int i = 0; i < 4; i++) {
                int k = bk0 + i * 8;
                const float* s = Bp + (size_t)(kk + k) * H + bc;
                uint32_t d = bb + (unsigned)(k * BN + bc) * 4u;
                cp16(d, s);
                cp16(d + 16, s + 4);
            }
            asm volatile("cp.async.commit_group;" ::: "memory");
        }
#pragma unroll 4
        for (int k = 0; k < BK; k++) {
            unsigned long long a2[8];
            const ulonglong2* arow = (const ulonglong2*)&As[buf][k][ty * 16];
#pragma unroll
            for (int j = 0; j < 4; j++) {
                ulonglong2 v = arow[j];
                a2[j * 2] = v.x;
                a2[j * 2 + 1] = v.y;
            }
            float b[8];
            *(float4*)&b[0] = *(const float4*)&Bs[buf][k][tx * 8];
            *(float4*)&b[4] = *(const float4*)&Bs[buf][k][tx * 8 + 4];
            unsigned long long bp[8];
#pragma unroll
            for (int c = 0; c < 8; c++) bp[c] = pack2(b[c]);
#pragma unroll
            for (int rp2 = 0; rp2 < 8; rp2++)
#pragma unroll
                for (int c = 0; c < 8; c++) ffma2(acc[rp2][c], a2[rp2], bp[c]);
        }
    }

    int col0 = tx * 8;
    if (MODE == 0) {
        float bv[8];
#pragma unroll
        for (int c = 0; c < 8; c++) bv[c] = bias ? bias[col0 + c] : 0.f;
#pragma unroll
        for (int rp2 = 0; rp2 < 8; rp2++) {
            float vlo[8], vhi[8];
#pragma unroll
            for (int c = 0; c < 8; c++) unpack2(acc[rp2][c], vlo[c], vhi[c]);
            int gr0 = row0 + ty * 16 + rp2 * 2;
#pragma unroll
            for (int h2 = 0; h2 < 2; h2++) {
                int gr = gr0 + h2;
                const float* v = h2 ? vhi : vlo;
                if (gr < NN) {
                    float o[8];
#pragma unroll
                    for (int c = 0; c < 8; c++) o[c] = v[c] + bv[c];
                    *(float4*)&out[(size_t)gr * ldo + ocol + col0] = *(float4*)o;
                    *(float4*)&out[(size_t)gr * ldo + ocol + col0 + 4] = *(float4*)(o + 4);
                }
            }
        }
    } else if (MODE == 2) {
        float bv[8];
#pragma unroll
        for (int c = 0; c < 8; c++) bv[c] = bias0[col0 + c];
#pragma unroll
        for (int rp2 = 0; rp2 < 8; rp2++) {
            float vlo[8], vhi[8];
#pragma unroll
            for (int c = 0; c < 8; c++) unpack2(acc[rp2][c], vlo[c], vhi[c]);
            int gr0 = row0 + ty * 16 + rp2 * 2;
#pragma unroll
            for (int h2 = 0; h2 < 2; h2++) {
                int gr = gr0 + h2;
                const float* v = h2 ? vhi : vlo;
                if (gr < NN) {
                    float o[8];
#pragma unroll
                    for (int c = 0; c < 8; c++) {
                        float t = fmaxf(v[c] + bv[c], 0.f);
                        o[c] = t + resid[(size_t)gr * H + col0 + c];
                    }
                    *(float4*)&out[(size_t)gr * ldo + col0] = *(float4*)o;
                    *(float4*)&out[(size_t)gr * ldo + col0 + 4] = *(float4*)(o + 4);
                }
            }
        }
    } else {
        float b2av[8], b2ev[8], gv[8], bbv[8];
        *(float4*)&b2av[0] = *(const float4*)&b2a[col0];
        *(float4*)&b2av[4] = *(const float4*)&b2a[col0 + 4];
        *(float4*)&b2ev[0] = *(const float4*)&b2e[col0];
        *(float4*)&b2ev[4] = *(const float4*)&b2e[col0 + 4];
        *(float4*)&gv[0] = *(const float4*)&lng[col0];
        *(float4*)&gv[4] = *(const float4*)&lng[col0 + 4];
        *(float4*)&bbv[0] = *(const float4*)&lnb[col0];
        *(float4*)&bbv[4] = *(const float4*)&lnb[col0 + 4];
#pragma unroll
        for (int rp2 = 0; rp2 < 8; rp2++) {
            float vlo[8], vhi[8];
#pragma unroll
            for (int c = 0; c < 8; c++) unpack2(acc[rp2][c], vlo[c], vhi[c]);
            int gr0 = row0 + ty * 16 + rp2 * 2;
#pragma unroll
            for (int h2 = 0; h2 < 2; h2++) {
                int gr = gr0 + h2;
                float* vv = h2 ? vhi : vlo;
                bool valid = gr < NN;
                float da = valid ? dega[gr] : 0.f;
                float de = valid ? dege[gr] : 0.f;
                float rs[8];
                if (valid) {
                    *(float4*)&rs[0] = *(const float4*)&resid[(size_t)gr * H + col0];
                    *(float4*)&rs[4] = *(const float4*)&resid[(size_t)gr * H + col0 + 4];
                } else {
#pragma unroll
                    for (int c = 0; c < 8; c++) rs[c] = 0.f;
                }
                float v[8];
                float s = 0.f, s2 = 0.f;
#pragma unroll
                for (int c = 0; c < 8; c++) {
                    v[c] = vv[c] + rs[c] + da * b2av[c] + de * b2ev[c];
                    s += v[c];
                    s2 += v[c] * v[c];
                }
#pragma unroll
                for (int off = 8; off; off >>= 1) {
                    s += __shfl_xor_sync(0xffffffffu, s, off);
                    s2 += __shfl_xor_sync(0xffffffffu, s2, off);
                }
                float mu = s * (1.f / 128.f);
                float var = s2 * (1.f / 128.f) - mu * mu;
                float rstd = rsqrtf(var + 1e-5f);
                if (valid) {
                    float o[8];
#pragma unroll
                    for (int c = 0; c < 8; c++) o[c] = (v[c] - mu) * rstd * gv[c] + bbv[c];
                    *(float4*)&out[(size_t)gr * H + col0] = *(float4*)o;
                    *(float4*)&out[(size_t)gr * H + col0 + 4] = *(float4*)(o + 4);
                }
            }
        }
    }
}

// ---------------- launch ----------------
extern "C" void kernel_launch(void* const* d_in, const int* in_sizes, int n_in,
                              void* d_out, int out_size) {
    (void)in_sizes; (void)n_in; (void)out_size;
    const float* x       = (const float*)d_in[0];
    const int*   ally_ei = (const int*)d_in[1];
    const float* ally_ea = (const float*)d_in[2];
    const int*   enc_ei  = (const int*)d_in[3];
    const float* enc_ea  = (const float*)d_in[4];
    const float* W_in    = (const float*)d_in[5];
    const float* b_in    = (const float*)d_in[6];
    const float* ally_W1 = (const float*)d_in[7];
    const float* ally_b1 = (const float*)d_in[8];
    const float* ally_W2 = (const float*)d_in[9];
    const float* ally_b2 = (const float*)d_in[10];
    const float* enc_W1  = (const float*)d_in[11];
    const float* enc_b1  = (const float*)d_in[12];
    const float* enc_W2  = (const float*)d_in[13];
    const float* enc_b2  = (const float*)d_in[14];
    const float* ln_g    = (const float*)d_in[15];
    const float* ln_b    = (const float*)d_in[16];
    const float* comb_W  = (const float*)d_in[17];
    const float* comb_b  = (const float*)d_in[18];
    float* out = (float*)d_out;

    float *h, *PQ, *S, *deg;
    int *cnt, *rp, *cur, *bsum;
    float4* edges;
    cudaGetSymbolAddress((void**)&h, g_h);
    cudaGetSymbolAddress((void**)&PQ, g_PQ);
    cudaGetSymbolAddress((void**)&S, g_S);
    cudaGetSymbolAddress((void**)&deg, g_deg);
    cudaGetSymbolAddress((void**)&cnt, g_cnt);
    cudaGetSymbolAddress((void**)&rp, g_rp);
    cudaGetSymbolAddress((void**)&cur, g_cur);
    cudaGetSymbolAddress((void**)&bsum, g_bsum);
    cudaGetSymbolAddress((void**)&edges, g_edges);
    float* dega = deg;
    float* dege = deg + NN;

    const int SMEM = (2 * BK * (BM + 4) + 2 * BK * BN) * 4;  // 66560 B
    cudaFuncSetAttribute(gemm_kernel<0>, cudaFuncAttributeMaxDynamicSharedMemorySize, SMEM);
    cudaFuncSetAttribute(gemm_kernel<1>, cudaFuncAttributeMaxDynamicSharedMemorySize, SMEM);
    cudaFuncSetAttribute(gemm_kernel<2>, cudaFuncAttributeMaxDynamicSharedMemorySize, SMEM);

    const int nblk = (NN + BM - 1) / BM;  // 782

    // ---- CSR build (once per call; shared by both layers) ----
    fill_zero<<<64, 256>>>((float4*)cnt, N2 / 4);
    hist_kernel<<<(2 * NE + 255) / 256, 256>>>(ally_ei, enc_ei, cnt);
    scan1<<<NB1, SCB>>>(cnt, rp, bsum);
    scan2<<<1, SCB>>>(bsum);
    scan3<<<NB1, SCB>>>(cnt, rp, bsum, cur, deg);
    fill_csr<<<(2 * NE + 255) / 256, 256>>>(ally_ei, ally_ea, enc_ei, enc_ea, cur, edges);

    // input projection
    input_proj<<<NN / IPN, 128>>>(x, W_in, b_in, h);

    for (int i = 0; i < 2; i++) {
        const float* aW1 = ally_W1 + (size_t)i * 258 * H;
        const float* eW1 = enc_W1 + (size_t)i * 258 * H;

        // P/Q for both edge types
        gemm_kernel<0><<<dim3(nblk, 4), 128, SMEM>>>(
            h, H, H,
            aW1, aW1 + 128 * H, eW1, eW1 + 128 * H,
            ally_b1 + i * H, enc_b1 + i * H,
            nullptr, nullptr, nullptr, nullptr, nullptr, nullptr, nullptr,
            PQ, 4 * H);

        // CSR edge pass: warp per target node, both edge sets, no atomics
        edge_csr<<<N2 / 8, 256>>>(rp, edges, PQ, aW1 + 256 * H, eW1 + 256 * H, S);

        // combine: h = LN(h + S_a@W2a + dega*b2a + S_e@W2e + dege*b2e)
        gemm_kernel<1><<<nblk, 128, SMEM>>>(
            S, 2 * H, 2 * H,
            ally_W2 + (size_t)i * H * H, enc_W2 + (size_t)i * H * H,
            nullptr, nullptr, nullptr, nullptr,
            h, dega, dege,
            ally_b2 + i * H, enc_b2 + i * H,
            ln_g + i * H, ln_b + i * H,
            h, H);

        // comb MLP: h = h + relu(h @ comb_W + comb_b); last layer writes d_out
        float* dst = (i == 1) ? out : h;
        gemm_kernel<2><<<nblk, 128, SMEM>>>(
            h, H, H,
            comb_W + (size_t)i * H * H, nullptr, nullptr, nullptr,
            comb_b + i * H, nullptr,
            h, nullptr, nullptr, nullptr, nullptr, nullptr, nullptr,
            dst, H);
    }
}

// round 10
// speedup vs baseline: 1.8503x; 1.0090x over previous
#include <cuda_runtime.h>
#include <cstdint>
#include <cstddef>

#define NN 100000
#define NE 600000
#define H 128
#define FIN 39

#define BM 128
#define BN 128
#define BK 32

#define N2 (2 * NN)                    // 200000 (ally nodes | enc nodes)
#define SCB 512
#define NB1 ((N2 + SCB - 1) / SCB)     // 391

// ---------------- scratch (device globals; no allocation allowed) ----------------
__device__ float g_h[(size_t)NN * H];        // node features          [N,128]
__device__ float g_PQ[(size_t)NN * 4 * H];   // P_a|Q_a|P_e|Q_e        [N,512]
__device__ float g_S[(size_t)NN * 2 * H];    // S_ally | S_enc         [N,256]
__device__ float g_deg[N2];                  // deg_ally | deg_enc (float)
__device__ int g_cnt[N2];                    // per-target edge counts
__device__ int g_rp[N2 + 1];                 // CSR row pointers (global over both sets)
__device__ int g_cur[N2];                    // fill cursors
__device__ int g_bsum[SCB];                  // scan block sums
__device__ __align__(16) float4 g_edges[2 * (size_t)NE];  // {src_bits, e0, e1, pad}

__device__ __forceinline__ void cp16(uint32_t dst, const float* src) {
    asm volatile("cp.async.cg.shared.global [%0], [%1], 16;" :: "r"(dst), "l"(src));
}
__device__ __forceinline__ void ffma2(unsigned long long& d, unsigned long long a,
                                      unsigned long long b) {
    asm("fma.rn.f32x2 %0, %1, %2, %0;" : "+l"(d) : "l"(a), "l"(b));
}
__device__ __forceinline__ unsigned long long pack2(float x) {
    unsigned long long r;
    asm("mov.b64 %0, {%1, %1};" : "=l"(r) : "f"(x));
    return r;
}
__device__ __forceinline__ void unpack2(unsigned long long v, float& lo, float& hi) {
    asm("mov.b64 {%0, %1}, %2;" : "=f"(lo), "=f"(hi) : "l"(v));
}

// ---------------- utility kernels ----------------
__global__ void fill_zero(float4* __restrict__ p, int n4) {
    int i = blockIdx.x * blockDim.x + threadIdx.x;
    int stride = gridDim.x * blockDim.x;
    float4 z = make_float4(0.f, 0.f, 0.f, 0.f);
    for (; i < n4; i += stride) p[i] = z;
}

// ---------------- CSR build ----------------
__global__ void hist_kernel(const int* __restrict__ eia, const int* __restrict__ eie,
                            int* __restrict__ cnt) {
    int t = blockIdx.x * blockDim.x + threadIdx.x;
    if (t < NE) {
        atomicAdd(&cnt[eia[NE + t]], 1);
    } else if (t < 2 * NE) {
        atomicAdd(&cnt[NN + eie[t]], 1);   // eie[NE + (t-NE)]
    }
}

__global__ void scan1(const int* __restrict__ cnt, int* __restrict__ rp,
                      int* __restrict__ bsum) {
    __shared__ int sh[SCB];
    int tid = threadIdx.x;
    int i = blockIdx.x * SCB + tid;
    int v = (i < N2) ? cnt[i] : 0;
    sh[tid] = v;
    __syncthreads();
    for (int off = 1; off < SCB; off <<= 1) {
        int t = (tid >= off) ? sh[tid - off] : 0;
        __syncthreads();
        sh[tid] += t;
        __syncthreads();
    }
    if (i < N2) rp[i] = sh[tid] - v;        // exclusive within block
    if (tid == SCB - 1) bsum[blockIdx.x] = sh[tid];
}

__global__ void scan2(int* __restrict__ bsum) {
    __shared__ int sh[SCB];
    int tid = threadIdx.x;
    int v = (tid < NB1) ? bsum[tid] : 0;
    sh[tid] = v;
    __syncthreads();
    for (int off = 1; off < SCB; off <<= 1) {
        int t = (tid >= off) ? sh[tid - off] : 0;
        __syncthreads();
        sh[tid] += t;
        __syncthreads();
    }
    if (tid < NB1) bsum[tid] = sh[tid] - v;  // exclusive
}

__global__ void scan3(const int* __restrict__ cnt, int* __restrict__ rp,
                      const int* __restrict__ bsum, int* __restrict__ cur,
                      float* __restrict__ deg) {
    int i = blockIdx.x * SCB + threadIdx.x;
    if (i < N2) {
        int e = rp[i] + bsum[blockIdx.x];
        rp[i] = e;
        cur[i] = e;
        deg[i] = (float)cnt[i];
    }
    if (i == 0) rp[N2] = 2 * NE;
}

__global__ void fill_csr(const int* __restrict__ eia, const float* __restrict__ eaa,
                         const int* __restrict__ eie, const float* __restrict__ eae,
                         int* __restrict__ cur, float4* __restrict__ edges) {
    int t = blockIdx.x * blockDim.x + threadIdx.x;
    if (t < NE) {
        int src = eia[t], tgt = eia[NE + t];
        int pos = atomicAdd(&cur[tgt], 1);
        edges[pos] = make_float4(__int_as_float(src), eaa[2 * t], eaa[2 * t + 1], 0.f);
    } else if (t < 2 * NE) {
        int e = t - NE;
        int src = eie[e], tgt = eie[NE + e];
        int pos = atomicAdd(&cur[NN + tgt], 1);
        edges[pos] = make_float4(__int_as_float(src), eae[2 * e], eae[2 * e + 1], 0.f);
    }
}

// ---------------- input projection: h = relu(x @ W_in + b_in) ----------------
#define IPN 16
__global__ void __launch_bounds__(128) input_proj(const float* __restrict__ x,
                                                  const float* __restrict__ Win,
                                                  const float* __restrict__ bin,
                                                  float* __restrict__ h) {
    __shared__ float Ws[FIN * H];
    __shared__ __align__(16) float xs[IPN][FIN + 1];
    int tid = threadIdx.x;
    for (int i = tid; i < FIN * H; i += 128) Ws[i] = Win[i];
    int n0 = blockIdx.x * IPN;
    for (int i = tid; i < IPN * FIN; i += 128) {
        int r = i / FIN, c = i - r * FIN;
        xs[r][c] = x[(size_t)(n0 + r) * FIN + c];
    }
    __syncthreads();
    float acc[IPN];
    float bv = bin[tid];
#pragma unroll
    for (int r = 0; r < IPN; r++) acc[r] = bv;
#pragma unroll
    for (int k4 = 0; k4 < 9; k4++) {
        float wv0 = Ws[(k4 * 4 + 0) * H + tid];
        float wv1 = Ws[(k4 * 4 + 1) * H + tid];
        float wv2 = Ws[(k4 * 4 + 2) * H + tid];
        float wv3 = Ws[(k4 * 4 + 3) * H + tid];
#pragma unroll
        for (int r = 0; r < IPN; r++) {
            float4 xv = *(const float4*)&xs[r][k4 * 4];
            acc[r] = fmaf(xv.x, wv0, acc[r]);
            acc[r] = fmaf(xv.y, wv1, acc[r]);
            acc[r] = fmaf(xv.z, wv2, acc[r]);
            acc[r] = fmaf(xv.w, wv3, acc[r]);
        }
    }
#pragma unroll
    for (int k = 36; k < FIN; k++) {
        float wv = Ws[k * H + tid];
#pragma unroll
        for (int r = 0; r < IPN; r++) acc[r] = fmaf(xs[r][k], wv, acc[r]);
    }
#pragma unroll
    for (int r = 0; r < IPN; r++)
        h[(size_t)(n0 + r) * H + tid] = fmaxf(acc[r], 0.f);
}

// ---------------- CSR edge pass: warp per target node, 2-edge unrolled gather ----------------
// S[node] = sum_j relu(P[node] + Q[src_j] + e0_j*w0 + e1_j*w1); degree-0 -> zeros.
__global__ void __launch_bounds__(256) edge_csr(
    const int* __restrict__ rp, const float4* __restrict__ edges,
    const float* __restrict__ PQ,
    const float* __restrict__ w1ca, const float* __restrict__ w1ce,
    float* __restrict__ S) {
    __shared__ __align__(16) float w[512];
    w[threadIdx.x] = w1ca[threadIdx.x];
    w[256 + threadIdx.x] = w1ce[threadIdx.x];
    __syncthreads();
    unsigned gw = blockIdx.x * 8u + (threadIdx.x >> 5);  // grid exactly N2/8 blocks
    int lane = threadIdx.x & 31;
    bool ally = gw < NN;
    int n = ally ? gw : gw - NN;
    size_t prow = (size_t)n * 512 + (ally ? 0 : 256);
    int qcol = ally ? 128 : 384;
    int woff = ally ? 0 : 256;
    int start = rp[gw], end = rp[gw + 1];

    float4 p = *(const float4*)&PQ[prow + lane * 4];
    float4 w0 = *(const float4*)&w[woff + lane * 4];
    float4 w1 = *(const float4*)&w[woff + 128 + lane * 4];
    float4 acc = make_float4(0.f, 0.f, 0.f, 0.f);

    int j = start;
    for (; j + 2 <= end; j += 2) {
        float4 er0 = edges[j];
        float4 er1 = edges[j + 1];
        int s0 = __float_as_int(er0.x);
        int s1 = __float_as_int(er1.x);
        // issue both gathers before consuming (MLP=2)
        float4 q0 = *(const float4*)&PQ[(size_t)s0 * 512 + qcol + lane * 4];
        float4 q1 = *(const float4*)&PQ[(size_t)s1 * 512 + qcol + lane * 4];
        float e00 = er0.y, e01 = er0.z;
        float e10 = er1.y, e11 = er1.z;
        acc.x += fmaxf(fmaf(e00, w0.x, fmaf(e01, w1.x, p.x + q0.x)), 0.f);
        acc.y += fmaxf(fmaf(e00, w0.y, fmaf(e01, w1.y, p.y + q0.y)), 0.f);
        acc.z += fmaxf(fmaf(e00, w0.z, fmaf(e01, w1.z, p.z + q0.z)), 0.f);
        acc.w += fmaxf(fmaf(e00, w0.w, fmaf(e01, w1.w, p.w + q0.w)), 0.f);
        acc.x += fmaxf(fmaf(e10, w0.x, fmaf(e11, w1.x, p.x + q1.x)), 0.f);
        acc.y += fmaxf(fmaf(e10, w0.y, fmaf(e11, w1.y, p.y + q1.y)), 0.f);
        acc.z += fmaxf(fmaf(e10, w0.z, fmaf(e11, w1.z, p.z + q1.z)), 0.f);
        acc.w += fmaxf(fmaf(e10, w0.w, fmaf(e11, w1.w, p.w + q1.w)), 0.f);
    }
    if (j < end) {
        float4 er = edges[j];
        int src = __float_as_int(er.x);
        float4 q = *(const float4*)&PQ[(size_t)src * 512 + qcol + lane * 4];
        float e0 = er.y, e1 = er.z;
        acc.x += fmaxf(fmaf(e0, w0.x, fmaf(e1, w1.x, p.x + q.x)), 0.f);
        acc.y += fmaxf(fmaf(e0, w0.y, fmaf(e1, w1.y, p.y + q.y)), 0.f);
        acc.z += fmaxf(fmaf(e0, w0.z, fmaf(e1, w1.z, p.z + q.z)), 0.f);
        acc.w += fmaxf(fmaf(e0, w0.w, fmaf(e1, w1.w, p.w + q.w)), 0.f);
    }
    *(float4*)&S[(size_t)n * 256 + (ally ? 0 : 128) + lane * 4] = acc;
}

// ---------------- 128x128 SGEMM, 128 threads, 16x8 micro-tile, FFMA2 (R4-proven) ------------
// MODE 0 (PQ):      out[:, y*128:(y+1)*128] = h @ B[y] (+bias y==0,2)
// MODE 1 (COMBINE): u = S@[W2a;W2e] + h + dega*b2a + dege*b2e; h = LayerNorm(u)
// MODE 2 (COMB):    out = resid + relu(h @ B0 + bias0)
template <int MODE>
__global__ void __launch_bounds__(128, 2) gemm_kernel(
    const float* __restrict__ A, int lda, int Ktot,
    const float* __restrict__ B0, const float* __restrict__ B1,
    const float* __restrict__ B2, const float* __restrict__ B3,
    const float* __restrict__ bias0, const float* __restrict__ bias2,
    const float* __restrict__ resid,
    const float* __restrict__ dega, const float* __restrict__ dege,
    const float* __restrict__ b2a, const float* __restrict__ b2e,
    const float* __restrict__ lng, const float* __restrict__ lnb,
    float* __restrict__ out, int ldo) {
    extern __shared__ float sm[];
    float(*As)[BK][BM + 4] = (float(*)[BK][BM + 4])sm;                  // [2][32][132]
    float(*Bs)[BK][BN] = (float(*)[BK][BN])(sm + 2 * BK * (BM + 4));    // [2][32][128]

    int tid = threadIdx.x;
    int tx = tid & 15;
    int ty = tid >> 4;
    int row0 = blockIdx.x * BM;

    const float* B = B0;
    const float* bias = bias0;
    int ocol = 0;
    if (MODE == 0) {
        int y = blockIdx.y;
        B = (y == 0) ? B0 : (y == 1) ? B1 : (y == 2) ? B2 : B3;
        bias = (y == 0) ? bias0 : (y == 2) ? bias2 : nullptr;
        ocol = y * BN;
    }

    int agr = row0 + tid;
    bool aval = agr < NN;
    const float* Aptr = A + (size_t)(aval ? agr : 0) * lda;
    int bk0 = tid >> 4;
    int bc = (tid & 15) * 8;

    uint32_t bs_base = (uint32_t)__cvta_generic_to_shared(&Bs[0][0][0]);

#pragma unroll
    for (int i = 0; i < 4; i++) {
        int k = bk0 + i * 8;
        const float* s = B + (size_t)k * H + bc;
        uint32_t d = bs_base + (unsigned)(k * BN + bc) * 4u;
        cp16(d, s);
        cp16(d + 16, s + 4);
    }
    asm volatile("cp.async.commit_group;" ::: "memory");

    float4 pa[8];
#pragma unroll
    for (int j = 0; j < 8; j++) pa[j] = *(const float4*)(Aptr + j * 4);

    unsigned long long acc[8][8];
#pragma unroll
    for (int rp2 = 0; rp2 < 8; rp2++)
#pragma unroll
        for (int c = 0; c < 8; c++) acc[rp2][c] = 0ull;

    const int niter = Ktot / BK;
    for (int it = 0; it < niter; it++) {
        int buf = it & 1;
        asm volatile("cp.async.wait_group 0;" ::: "memory");
#pragma unroll
        for (int j = 0; j < 8; j++) {
            int k0 = j * 4;
            As[buf][k0 + 0][tid] = pa[j].x;
            As[buf][k0 + 1][tid] = pa[j].y;
            As[buf][k0 + 2][tid] = pa[j].z;
            As[buf][k0 + 3][tid] = pa[j].w;
        }
        if (it + 1 < niter) {
            const float* ap = Aptr + (it + 1) * BK;
#pragma unroll
            for (int j = 0; j < 8; j++) pa[j] = *(const float4*)(ap + j * 4);
        }
        __syncthreads();
        if (it + 1 < niter) {
            int kb2 = (it + 1) * BK;
            const float* Bp = B;
            int kk = kb2;
            if (MODE == 1 && kb2 >= H) { Bp = B1; kk = kb2 - H; }
            uint32_t bb = bs_base + (unsigned)((buf ^ 1) * BK * BN) * 4u;
#pragma unroll
            for (int i = 0; i < 4; i++) {
                int k = bk0 + i * 8;
                const float* s = Bp + (size_t)(kk + k) * H + bc;
                uint32_t d = bb + (unsigned)(k * BN + bc) * 4u;
                cp16(d, s);
                cp16(d + 16, s + 4);
            }
            asm volatile("cp.async.commit_group;" ::: "memory");
        }
#pragma unroll 4
        for (int k = 0; k < BK; k++) {
            unsigned long long a2[8];
            const ulonglong2* arow = (const ulonglong2*)&As[buf][k][ty * 16];
#pragma unroll
            for (int j = 0; j < 4; j++) {
                ulonglong2 v = arow[j];
                a2[j * 2] = v.x;
                a2[j * 2 + 1] = v.y;
            }
            float b[8];
            *(float4*)&b[0] = *(const float4*)&Bs[buf][k][tx * 8];
            *(float4*)&b[4] = *(const float4*)&Bs[buf][k][tx * 8 + 4];
            unsigned long long bp[8];
#pragma unroll
            for (int c = 0; c < 8; c++) bp[c] = pack2(b[c]);
#pragma unroll
            for (int rp2 = 0; rp2 < 8; rp2++)
#pragma unroll
                for (int c = 0; c < 8; c++) ffma2(acc[rp2][c], a2[rp2], bp[c]);
        }
    }

    int col0 = tx * 8;
    if (MODE == 0) {
        float bv[8];
#pragma unroll
        for (int c = 0; c < 8; c++) bv[c] = bias ? bias[col0 + c] : 0.f;
#pragma unroll
        for (int rp2 = 0; rp2 < 8; rp2++) {
            float vlo[8], vhi[8];
#pragma unroll
            for (int c = 0; c < 8; c++) unpack2(acc[rp2][c], vlo[c], vhi[c]);
            int gr0 = row0 + ty * 16 + rp2 * 2;
#pragma unroll
            for (int h2 = 0; h2 < 2; h2++) {
                int gr = gr0 + h2;
                const float* v = h2 ? vhi : vlo;
                if (gr < NN) {
                    float o[8];
#pragma unroll
                    for (int c = 0; c < 8; c++) o[c] = v[c] + bv[c];
                    *(float4*)&out[(size_t)gr * ldo + ocol + col0] = *(float4*)o;
                    *(float4*)&out[(size_t)gr * ldo + ocol + col0 + 4] = *(float4*)(o + 4);
                }
            }
        }
    } else if (MODE == 2) {
        float bv[8];
#pragma unroll
        for (int c = 0; c < 8; c++) bv[c] = bias0[col0 + c];
#pragma unroll
        for (int rp2 = 0; rp2 < 8; rp2++) {
            float vlo[8], vhi[8];
#pragma unroll
            for (int c = 0; c < 8; c++) unpack2(acc[rp2][c], vlo[c], vhi[c]);
            int gr0 = row0 + ty * 16 + rp2 * 2;
#pragma unroll
            for (int h2 = 0; h2 < 2; h2++) {
                int gr = gr0 + h2;
                const float* v = h2 ? vhi : vlo;
                if (gr < NN) {
                    float o[8];
#pragma unroll
                    for (int c = 0; c < 8; c++) {
                        float t = fmaxf(v[c] + bv[c], 0.f);
                        o[c] = t + resid[(size_t)gr * H + col0 + c];
                    }
                    *(float4*)&out[(size_t)gr * ldo + col0] = *(float4*)o;
                    *(float4*)&out[(size_t)gr * ldo + col0 + 4] = *(float4*)(o + 4);
                }
            }
        }
    } else {
        float b2av[8], b2ev[8], gv[8], bbv[8];
        *(float4*)&b2av[0] = *(const float4*)&b2a[col0];
        *(float4*)&b2av[4] = *(const float4*)&b2a[col0 + 4];
        *(float4*)&b2ev[0] = *(const float4*)&b2e[col0];
        *(float4*)&b2ev[4] = *(const float4*)&b2e[col0 + 4];
        *(float4*)&gv[0] = *(const float4*)&lng[col0];
        *(float4*)&gv[4] = *(const float4*)&lng[col0 + 4];
        *(float4*)&bbv[0] = *(const float4*)&lnb[col0];
        *(float4*)&bbv[4] = *(const float4*)&lnb[col0 + 4];
#pragma unroll
        for (int rp2 = 0; rp2 < 8; rp2++) {
            float vlo[8], vhi[8];
#pragma unroll
            for (int c = 0; c < 8; c++) unpack2(acc[rp2][c], vlo[c], vhi[c]);
            int gr0 = row0 + ty * 16 + rp2 * 2;
#pragma unroll
            for (int h2 = 0; h2 < 2; h2++) {
                int gr = gr0 + h2;
                float* vv = h2 ? vhi : vlo;
                bool valid = gr < NN;
                float da = valid ? dega[gr] : 0.f;
                float de = valid ? dege[gr] : 0.f;
                float rs[8];
                if (valid) {
                    *(float4*)&rs[0] = *(const float4*)&resid[(size_t)gr * H + col0];
                    *(float4*)&rs[4] = *(const float4*)&resid[(size_t)gr * H + col0 + 4];
                } else {
#pragma unroll
                    for (int c = 0; c < 8; c++) rs[c] = 0.f;
                }
                float v[8];
                float s = 0.f, s2 = 0.f;
#pragma unroll
                for (int c = 0; c < 8; c++) {
                    v[c] = vv[c] + rs[c] + da * b2av[c] + de * b2ev[c];
                    s += v[c];
                    s2 += v[c] * v[c];
                }
#pragma unroll
                for (int off = 8; off; off >>= 1) {
                    s += __shfl_xor_sync(0xffffffffu, s, off);
                    s2 += __shfl_xor_sync(0xffffffffu, s2, off);
                }
                float mu = s * (1.f / 128.f);
                float var = s2 * (1.f / 128.f) - mu * mu;
                float rstd = rsqrtf(var + 1e-5f);
                if (valid) {
                    float o[8];
#pragma unroll
                    for (int c = 0; c < 8; c++) o[c] = (v[c] - mu) * rstd * gv[c] + bbv[c];
                    *(float4*)&out[(size_t)gr * H + col0] = *(float4*)o;
                    *(float4*)&out[(size_t)gr * H + col0 + 4] = *(float4*)(o + 4);
                }
            }
        }
    }
}

// ---------------- launch ----------------
extern "C" void kernel_launch(void* const* d_in, const int* in_sizes, int n_in,
                              void* d_out, int out_size) {
    (void)in_sizes; (void)n_in; (void)out_size;
    const float* x       = (const float*)d_in[0];
    const int*   ally_ei = (const int*)d_in[1];
    const float* ally_ea = (const float*)d_in[2];
    const int*   enc_ei  = (const int*)d_in[3];
    const float* enc_ea  = (const float*)d_in[4];
    const float* W_in    = (const float*)d_in[5];
    const float* b_in    = (const float*)d_in[6];
    const float* ally_W1 = (const float*)d_in[7];
    const float* ally_b1 = (const float*)d_in[8];
    const float* ally_W2 = (const float*)d_in[9];
    const float* ally_b2 = (const float*)d_in[10];
    const float* enc_W1  = (const float*)d_in[11];
    const float* enc_b1  = (const float*)d_in[12];
    const float* enc_W2  = (const float*)d_in[13];
    const float* enc_b2  = (const float*)d_in[14];
    const float* ln_g    = (const float*)d_in[15];
    const float* ln_b    = (const float*)d_in[16];
    const float* comb_W  = (const float*)d_in[17];
    const float* comb_b  = (const float*)d_in[18];
    float* out = (float*)d_out;

    float *h, *PQ, *S, *deg;
    int *cnt, *rp, *cur, *bsum;
    float4* edges;
    cudaGetSymbolAddress((void**)&h, g_h);
    cudaGetSymbolAddress((void**)&PQ, g_PQ);
    cudaGetSymbolAddress((void**)&S, g_S);
    cudaGetSymbolAddress((void**)&deg, g_deg);
    cudaGetSymbolAddress((void**)&cnt, g_cnt);
    cudaGetSymbolAddress((void**)&rp, g_rp);
    cudaGetSymbolAddress((void**)&cur, g_cur);
    cudaGetSymbolAddress((void**)&bsum, g_bsum);
    cudaGetSymbolAddress((void**)&edges, g_edges);
    float* dega = deg;
    float* dege = deg + NN;

    const int SMEM = (2 * BK * (BM + 4) + 2 * BK * BN) * 4;  // 66560 B
    cudaFuncSetAttribute(gemm_kernel<0>, cudaFuncAttributeMaxDynamicSharedMemorySize, SMEM);
    cudaFuncSetAttribute(gemm_kernel<1>, cudaFuncAttributeMaxDynamicSharedMemorySize, SMEM);
    cudaFuncSetAttribute(gemm_kernel<2>, cudaFuncAttributeMaxDynamicSharedMemorySize, SMEM);

    const int nblk = (NN + BM - 1) / BM;  // 782

    // ---- CSR build (once per call; shared by both layers) ----
    fill_zero<<<64, 256>>>((float4*)cnt, N2 / 4);
    hist_kernel<<<(2 * NE + 255) / 256, 256>>>(ally_ei, enc_ei, cnt);
    scan1<<<NB1, SCB>>>(cnt, rp, bsum);
    scan2<<<1, SCB>>>(bsum);
    scan3<<<NB1, SCB>>>(cnt, rp, bsum, cur, deg);
    fill_csr<<<(2 * NE + 255) / 256, 256>>>(ally_ei, ally_ea, enc_ei, enc_ea, cur, edges);

    // input projection
    input_proj<<<NN / IPN, 128>>>(x, W_in, b_in, h);

    for (int i = 0; i < 2; i++) {
        const float* aW1 = ally_W1 + (size_t)i * 258 * H;
        const float* eW1 = enc_W1 + (size_t)i * 258 * H;

        // P/Q for both edge types
        gemm_kernel<0><<<dim3(nblk, 4), 128, SMEM>>>(
            h, H, H,
            aW1, aW1 + 128 * H, eW1, eW1 + 128 * H,
            ally_b1 + i * H, enc_b1 + i * H,
            nullptr, nullptr, nullptr, nullptr, nullptr, nullptr, nullptr,
            PQ, 4 * H);

        // CSR edge pass: warp per target node, both edge sets, no atomics
        edge_csr<<<N2 / 8, 256>>>(rp, edges, PQ, aW1 + 256 * H, eW1 + 256 * H, S);

        // combine: h = LN(h + S_a@W2a + dega*b2a + S_e@W2e + dege*b2e)
        gemm_kernel<1><<<nblk, 128, SMEM>>>(
            S, 2 * H, 2 * H,
            ally_W2 + (size_t)i * H * H, enc_W2 + (size_t)i * H * H,
            nullptr, nullptr, nullptr, nullptr,
            h, dega, dege,
            ally_b2 + i * H, enc_b2 + i * H,
            ln_g + i * H, ln_b + i * H,
            h, H);

        // comb MLP: h = h + relu(h @ comb_W + comb_b); last layer writes d_out
        float* dst = (i == 1) ? out : h;
        gemm_kernel<2><<<nblk, 128, SMEM>>>(
            h, H, H,
            comb_W + (size_t)i * H * H, nullptr, nullptr, nullptr,
            comb_b + i * H, nullptr,
            h, nullptr, nullptr, nullptr, nullptr, nullptr, nullptr,
            dst, H);
    }
}

// round 11
// speedup vs baseline: 1.8683x; 1.0097x over previous
#include <cuda_runtime.h>
#include <cstdint>
#include <cstddef>

#define NN 100000
#define NE 600000
#define H 128
#define FIN 39

#define BM 128
#define BN 128
#define BK 32

#define N2 (2 * NN)
#define SCB 512
#define NB1 ((N2 + SCB - 1) / SCB)

// ---------------- scratch (device globals; no allocation allowed) ----------------
__device__ float g_h[(size_t)NN * H];
__device__ float g_PQ[(size_t)NN * 4 * H];
__device__ float g_S[(size_t)NN * 2 * H];
__device__ float g_deg[N2];
__device__ int g_cnt[N2];
__device__ int g_rp[N2 + 1];
__device__ int g_cur[N2];
__device__ int g_bsum[SCB];
__device__ __align__(16) float4 g_edges[2 * (size_t)NE];

__device__ __forceinline__ void cp16(uint32_t dst, const float* src) {
    asm volatile("cp.async.cg.shared.global [%0], [%1], 16;" :: "r"(dst), "l"(src));
}
__device__ __forceinline__ void ffma2(unsigned long long& d, unsigned long long a,
                                      unsigned long long b) {
    asm("fma.rn.f32x2 %0, %1, %2, %0;" : "+l"(d) : "l"(a), "l"(b));
}
__device__ __forceinline__ unsigned long long pack2(float x) {
    unsigned long long r;
    asm("mov.b64 %0, {%1, %1};" : "=l"(r) : "f"(x));
    return r;
}
__device__ __forceinline__ void unpack2(unsigned long long v, float& lo, float& hi) {
    asm("mov.b64 {%0, %1}, %2;" : "=f"(lo), "=f"(hi) : "l"(v));
}

// ---------------- utility kernels ----------------
__global__ void fill_zero(float4* __restrict__ p, int n4) {
    int i = blockIdx.x * blockDim.x + threadIdx.x;
    int stride = gridDim.x * blockDim.x;
    float4 z = make_float4(0.f, 0.f, 0.f, 0.f);
    for (; i < n4; i += stride) p[i] = z;
}

// ---------------- CSR build ----------------
__global__ void hist_kernel(const int* __restrict__ eia, const int* __restrict__ eie,
                            int* __restrict__ cnt) {
    int t = blockIdx.x * blockDim.x + threadIdx.x;
    if (t < NE) {
        atomicAdd(&cnt[eia[NE + t]], 1);
    } else if (t < 2 * NE) {
        atomicAdd(&cnt[NN + eie[t]], 1);
    }
}

__global__ void scan1(const int* __restrict__ cnt, int* __restrict__ rp,
                      int* __restrict__ bsum) {
    __shared__ int sh[SCB];
    int tid = threadIdx.x;
    int i = blockIdx.x * SCB + tid;
    int v = (i < N2) ? cnt[i] : 0;
    sh[tid] = v;
    __syncthreads();
    for (int off = 1; off < SCB; off <<= 1) {
        int t = (tid >= off) ? sh[tid - off] : 0;
        __syncthreads();
        sh[tid] += t;
        __syncthreads();
    }
    if (i < N2) rp[i] = sh[tid] - v;
    if (tid == SCB - 1) bsum[blockIdx.x] = sh[tid];
}

__global__ void scan2(int* __restrict__ bsum) {
    __shared__ int sh[SCB];
    int tid = threadIdx.x;
    int v = (tid < NB1) ? bsum[tid] : 0;
    sh[tid] = v;
    __syncthreads();
    for (int off = 1; off < SCB; off <<= 1) {
        int t = (tid >= off) ? sh[tid - off] : 0;
        __syncthreads();
        sh[tid] += t;
        __syncthreads();
    }
    if (tid < NB1) bsum[tid] = sh[tid] - v;
}

__global__ void scan3(const int* __restrict__ cnt, int* __restrict__ rp,
                      const int* __restrict__ bsum, int* __restrict__ cur,
                      float* __restrict__ deg) {
    int i = blockIdx.x * SCB + threadIdx.x;
    if (i < N2) {
        int e = rp[i] + bsum[blockIdx.x];
        rp[i] = e;
        cur[i] = e;
        deg[i] = (float)cnt[i];
    }
    if (i == 0) rp[N2] = 2 * NE;
}

__global__ void fill_csr(const int* __restrict__ eia, const float* __restrict__ eaa,
                         const int* __restrict__ eie, const float* __restrict__ eae,
                         int* __restrict__ cur, float4* __restrict__ edges) {
    int t = blockIdx.x * blockDim.x + threadIdx.x;
    if (t < NE) {
        int src = eia[t], tgt = eia[NE + t];
        int pos = atomicAdd(&cur[tgt], 1);
        edges[pos] = make_float4(__int_as_float(src), eaa[2 * t], eaa[2 * t + 1], 0.f);
    } else if (t < 2 * NE) {
        int e = t - NE;
        int src = eie[e], tgt = eie[NE + e];
        int pos = atomicAdd(&cur[NN + tgt], 1);
        edges[pos] = make_float4(__int_as_float(src), eae[2 * e], eae[2 * e + 1], 0.f);
    }
}

// ---------------- input projection ----------------
#define IPN 16
__global__ void __launch_bounds__(128) input_proj(const float* __restrict__ x,
                                                  const float* __restrict__ Win,
                                                  const float* __restrict__ bin,
                                                  float* __restrict__ h) {
    __shared__ float Ws[FIN * H];
    __shared__ __align__(16) float xs[IPN][FIN + 1];
    int tid = threadIdx.x;
    for (int i = tid; i < FIN * H; i += 128) Ws[i] = Win[i];
    int n0 = blockIdx.x * IPN;
    for (int i = tid; i < IPN * FIN; i += 128) {
        int r = i / FIN, c = i - r * FIN;
        xs[r][c] = x[(size_t)(n0 + r) * FIN + c];
    }
    __syncthreads();
    float acc[IPN];
    float bv = bin[tid];
#pragma unroll
    for (int r = 0; r < IPN; r++) acc[r] = bv;
#pragma unroll
    for (int k4 = 0; k4 < 9; k4++) {
        float wv0 = Ws[(k4 * 4 + 0) * H + tid];
        float wv1 = Ws[(k4 * 4 + 1) * H + tid];
        float wv2 = Ws[(k4 * 4 + 2) * H + tid];
        float wv3 = Ws[(k4 * 4 + 3) * H + tid];
#pragma unroll
        for (int r = 0; r < IPN; r++) {
            float4 xv = *(const float4*)&xs[r][k4 * 4];
            acc[r] = fmaf(xv.x, wv0, acc[r]);
            acc[r] = fmaf(xv.y, wv1, acc[r]);
            acc[r] = fmaf(xv.z, wv2, acc[r]);
            acc[r] = fmaf(xv.w, wv3, acc[r]);
        }
    }
#pragma unroll
    for (int k = 36; k < FIN; k++) {
        float wv = Ws[k * H + tid];
#pragma unroll
        for (int r = 0; r < IPN; r++) acc[r] = fmaf(xs[r][k], wv, acc[r]);
    }
#pragma unroll
    for (int r = 0; r < IPN; r++)
        h[(size_t)(n0 + r) * H + tid] = fmaxf(acc[r], 0.f);
}

// ---------------- CSR edge pass (R10-proven) ----------------
__global__ void __launch_bounds__(256) edge_csr(
    const int* __restrict__ rp, const float4* __restrict__ edges,
    const float* __restrict__ PQ,
    const float* __restrict__ w1ca, const float* __restrict__ w1ce,
    float* __restrict__ S) {
    __shared__ __align__(16) float w[512];
    w[threadIdx.x] = w1ca[threadIdx.x];
    w[256 + threadIdx.x] = w1ce[threadIdx.x];
    __syncthreads();
    unsigned gw = blockIdx.x * 8u + (threadIdx.x >> 5);
    int lane = threadIdx.x & 31;
    bool ally = gw < NN;
    int n = ally ? gw : gw - NN;
    size_t prow = (size_t)n * 512 + (ally ? 0 : 256);
    int qcol = ally ? 128 : 384;
    int woff = ally ? 0 : 256;
    int start = rp[gw], end = rp[gw + 1];

    float4 p = *(const float4*)&PQ[prow + lane * 4];
    float4 w0 = *(const float4*)&w[woff + lane * 4];
    float4 w1 = *(const float4*)&w[woff + 128 + lane * 4];
    float4 acc = make_float4(0.f, 0.f, 0.f, 0.f);

    int j = start;
    for (; j + 2 <= end; j += 2) {
        float4 er0 = edges[j];
        float4 er1 = edges[j + 1];
        int s0 = __float_as_int(er0.x);
        int s1 = __float_as_int(er1.x);
        float4 q0 = *(const float4*)&PQ[(size_t)s0 * 512 + qcol + lane * 4];
        float4 q1 = *(const float4*)&PQ[(size_t)s1 * 512 + qcol + lane * 4];
        float e00 = er0.y, e01 = er0.z;
        float e10 = er1.y, e11 = er1.z;
        acc.x += fmaxf(fmaf(e00, w0.x, fmaf(e01, w1.x, p.x + q0.x)), 0.f);
        acc.y += fmaxf(fmaf(e00, w0.y, fmaf(e01, w1.y, p.y + q0.y)), 0.f);
        acc.z += fmaxf(fmaf(e00, w0.z, fmaf(e01, w1.z, p.z + q0.z)), 0.f);
        acc.w += fmaxf(fmaf(e00, w0.w, fmaf(e01, w1.w, p.w + q0.w)), 0.f);
        acc.x += fmaxf(fmaf(e10, w0.x, fmaf(e11, w1.x, p.x + q1.x)), 0.f);
        acc.y += fmaxf(fmaf(e10, w0.y, fmaf(e11, w1.y, p.y + q1.y)), 0.f);
        acc.z += fmaxf(fmaf(e10, w0.z, fmaf(e11, w1.z, p.z + q1.z)), 0.f);
        acc.w += fmaxf(fmaf(e10, w0.w, fmaf(e11, w1.w, p.w + q1.w)), 0.f);
    }
    if (j < end) {
        float4 er = edges[j];
        int src = __float_as_int(er.x);
        float4 q = *(const float4*)&PQ[(size_t)src * 512 + qcol + lane * 4];
        float e0 = er.y, e1 = er.z;
        acc.x += fmaxf(fmaf(e0, w0.x, fmaf(e1, w1.x, p.x + q.x)), 0.f);
        acc.y += fmaxf(fmaf(e0, w0.y, fmaf(e1, w1.y, p.y + q.y)), 0.f);
        acc.z += fmaxf(fmaf(e0, w0.z, fmaf(e1, w1.z, p.z + q.z)), 0.f);
        acc.w += fmaxf(fmaf(e0, w0.w, fmaf(e1, w1.w, p.w + q.w)), 0.f);
    }
    *(float4*)&S[(size_t)n * 256 + (ally ? 0 : 128) + lane * 4] = acc;
}

// ---------------- gemm0: PQ projections (R4-proven config, MODE0 only) ----------------
__global__ void __launch_bounds__(128, 2) gemm0_kernel(
    const float* __restrict__ A,
    const float* __restrict__ B0, const float* __restrict__ B1,
    const float* __restrict__ B2, const float* __restrict__ B3,
    const float* __restrict__ bias0, const float* __restrict__ bias2,
    float* __restrict__ out) {
    extern __shared__ float sm[];
    float(*As)[BK][BM + 4] = (float(*)[BK][BM + 4])sm;
    float(*Bs)[BK][BN] = (float(*)[BK][BN])(sm + 2 * BK * (BM + 4));

    int tid = threadIdx.x;
    int tx = tid & 15;
    int ty = tid >> 4;
    int row0 = blockIdx.x * BM;

    int y = blockIdx.y;
    const float* B = (y == 0) ? B0 : (y == 1) ? B1 : (y == 2) ? B2 : B3;
    const float* bias = (y == 0) ? bias0 : (y == 2) ? bias2 : nullptr;
    int ocol = y * BN;

    int agr = row0 + tid;
    bool aval = agr < NN;
    const float* Aptr = A + (size_t)(aval ? agr : 0) * H;
    int bk0 = tid >> 4;
    int bc = (tid & 15) * 8;

    uint32_t bs_base = (uint32_t)__cvta_generic_to_shared(&Bs[0][0][0]);

#pragma unroll
    for (int i = 0; i < 4; i++) {
        int k = bk0 + i * 8;
        const float* s = B + (size_t)k * H + bc;
        uint32_t d = bs_base + (unsigned)(k * BN + bc) * 4u;
        cp16(d, s);
        cp16(d + 16, s + 4);
    }
    asm volatile("cp.async.commit_group;" ::: "memory");

    float4 pa[8];
#pragma unroll
    for (int j = 0; j < 8; j++) pa[j] = *(const float4*)(Aptr + j * 4);

    unsigned long long acc[8][8];
#pragma unroll
    for (int rp2 = 0; rp2 < 8; rp2++)
#pragma unroll
        for (int c = 0; c < 8; c++) acc[rp2][c] = 0ull;

    for (int it = 0; it < 4; it++) {
        int buf = it & 1;
        asm volatile("cp.async.wait_group 0;" ::: "memory");
#pragma unroll
        for (int j = 0; j < 8; j++) {
            int k0 = j * 4;
            As[buf][k0 + 0][tid] = pa[j].x;
            As[buf][k0 + 1][tid] = pa[j].y;
            As[buf][k0 + 2][tid] = pa[j].z;
            As[buf][k0 + 3][tid] = pa[j].w;
        }
        if (it + 1 < 4) {
            const float* ap = Aptr + (it + 1) * BK;
#pragma unroll
            for (int j = 0; j < 8; j++) pa[j] = *(const float4*)(ap + j * 4);
        }
        __syncthreads();
        if (it + 1 < 4) {
            int kk = (it + 1) * BK;
            uint32_t bb = bs_base + (unsigned)((buf ^ 1) * BK * BN) * 4u;
#pragma unroll
            for (int i = 0; i < 4; i++) {
                int k = bk0 + i * 8;
                const float* s = B + (size_t)(kk + k) * H + bc;
                uint32_t d = bb + (unsigned)(k * BN + bc) * 4u;
                cp16(d, s);
                cp16(d + 16, s + 4);
            }
            asm volatile("cp.async.commit_group;" ::: "memory");
        }
#pragma unroll 4
        for (int k = 0; k < BK; k++) {
            unsigned long long a2[8];
            const ulonglong2* arow = (const ulonglong2*)&As[buf][k][ty * 16];
#pragma unroll
            for (int j = 0; j < 4; j++) {
                ulonglong2 v = arow[j];
                a2[j * 2] = v.x;
                a2[j * 2 + 1] = v.y;
            }
            float b[8];
            *(float4*)&b[0] = *(const float4*)&Bs[buf][k][tx * 8];
            *(float4*)&b[4] = *(const float4*)&Bs[buf][k][tx * 8 + 4];
            unsigned long long bp[8];
#pragma unroll
            for (int c = 0; c < 8; c++) bp[c] = pack2(b[c]);
#pragma unroll
            for (int rp2 = 0; rp2 < 8; rp2++)
#pragma unroll
                for (int c = 0; c < 8; c++) ffma2(acc[rp2][c], a2[rp2], bp[c]);
        }
    }

    int col0 = tx * 8;
    float bv[8];
#pragma unroll
    for (int c = 0; c < 8; c++) bv[c] = bias ? bias[col0 + c] : 0.f;
#pragma unroll
    for (int rp2 = 0; rp2 < 8; rp2++) {
        float vlo[8], vhi[8];
#pragma unroll
        for (int c = 0; c < 8; c++) unpack2(acc[rp2][c], vlo[c], vhi[c]);
        int gr0 = row0 + ty * 16 + rp2 * 2;
#pragma unroll
        for (int h2 = 0; h2 < 2; h2++) {
            int gr = gr0 + h2;
            const float* v = h2 ? vhi : vlo;
            if (gr < NN) {
                float o[8];
#pragma unroll
                for (int c = 0; c < 8; c++) o[c] = v[c] + bv[c];
                *(float4*)&out[(size_t)gr * 512 + ocol + col0] = *(float4*)o;
                *(float4*)&out[(size_t)gr * 512 + ocol + col0 + 4] = *(float4*)(o + 4);
            }
        }
    }
}

// ---------------- fused gemm12: u = S@[W2a;W2e]+h+deg*b2 ; v = LN(u) ;
//                  out = v + relu(v @ Wc + bc)   (v never leaves smem) ----------------
// smem (floats): [0,8448) As | [8448,16640) Bs  (first GEMM, double-buffered)
//                [0,16384) vsm (swizzled transposed LN tile; reused after first GEMM)
//                [16640,24832) Bs2 (comb_W, double-buffered)
#define SM12_FLOATS 24832
__global__ void __launch_bounds__(128, 2) gemm12_kernel(
    const float* __restrict__ Sm,
    const float* __restrict__ B0, const float* __restrict__ B1,
    const float* __restrict__ Wc, const float* __restrict__ bc,
    const float* __restrict__ resid,
    const float* __restrict__ dega, const float* __restrict__ dege,
    const float* __restrict__ b2a, const float* __restrict__ b2e,
    const float* __restrict__ lng, const float* __restrict__ lnb,
    float* __restrict__ out) {
    extern __shared__ float sm[];
    float(*As)[BK][BM + 4] = (float(*)[BK][BM + 4])sm;
    float(*Bs)[BK][BN] = (float(*)[BK][BN])(sm + 8448);
    float* vsm = sm;                                       // [128][128] swizzled
    float(*Bs2)[BK][BN] = (float(*)[BK][BN])(sm + 16640);

    int tid = threadIdx.x;
    int tx = tid & 15;
    int ty = tid >> 4;
    int row0 = blockIdx.x * BM;
    int col0 = tx * 8;

    int agr = row0 + tid;
    bool aval = agr < NN;
    const float* Aptr = Sm + (size_t)(aval ? agr : 0) * 256;
    int bk0 = tid >> 4;
    int bc8 = (tid & 15) * 8;

    uint32_t bs_base = (uint32_t)__cvta_generic_to_shared(&Bs[0][0][0]);
    uint32_t bs2_base = (uint32_t)__cvta_generic_to_shared(&Bs2[0][0][0]);

    // prologue: comb_W tile0 -> Bs2[0]; W2a tile0 -> Bs[0]; A(0) -> regs
#pragma unroll
    for (int i = 0; i < 4; i++) {
        int k = bk0 + i * 8;
        const float* s = Wc + (size_t)k * H + bc8;
        uint32_t d = bs2_base + (unsigned)(k * BN + bc8) * 4u;
        cp16(d, s);
        cp16(d + 16, s + 4);
    }
#pragma unroll
    for (int i = 0; i < 4; i++) {
        int k = bk0 + i * 8;
        const float* s = B0 + (size_t)k * H + bc8;
        uint32_t d = bs_base + (unsigned)(k * BN + bc8) * 4u;
        cp16(d, s);
        cp16(d + 16, s + 4);
    }
    asm volatile("cp.async.commit_group;" ::: "memory");

    float4 pa[8];
#pragma unroll
    for (int j = 0; j < 8; j++) pa[j] = *(const float4*)(Aptr + j * 4);

    unsigned long long acc[8][8];
#pragma unroll
    for (int rp2 = 0; rp2 < 8; rp2++)
#pragma unroll
        for (int c = 0; c < 8; c++) acc[rp2][c] = 0ull;

    // ---- first GEMM: K=256 over [W2a; W2e] ----
    for (int it = 0; it < 8; it++) {
        int buf = it & 1;
        asm volatile("cp.async.wait_group 0;" ::: "memory");
#pragma unroll
        for (int j = 0; j < 8; j++) {
            int k0 = j * 4;
            As[buf][k0 + 0][tid] = pa[j].x;
            As[buf][k0 + 1][tid] = pa[j].y;
            As[buf][k0 + 2][tid] = pa[j].z;
            As[buf][k0 + 3][tid] = pa[j].w;
        }
        if (it + 1 < 8) {
            const float* ap = Aptr + (it + 1) * BK;
#pragma unroll
            for (int j = 0; j < 8; j++) pa[j] = *(const float4*)(ap + j * 4);
        }
        __syncthreads();
        if (it + 1 < 8) {
            int kb2 = (it + 1) * BK;
            const float* Bp = B0;
            int kk = kb2;
            if (kb2 >= H) { Bp = B1; kk = kb2 - H; }
            uint32_t bb = bs_base + (unsigned)((buf ^ 1) * BK * BN) * 4u;
#pragma unroll
            for (int i = 0; i < 4; i++) {
                int k = bk0 + i * 8;
                const float* s = Bp + (size_t)(kk + k) * H + bc8;
                uint32_t d = bb + (unsigned)(k * BN + bc8) * 4u;
                cp16(d, s);
                cp16(d + 16, s + 4);
            }
            asm volatile("cp.async.commit_group;" ::: "memory");
        }
#pragma unroll 4
        for (int k = 0; k < BK; k++) {
            unsigned long long a2[8];
            const ulonglong2* arow = (const ulonglong2*)&As[buf][k][ty * 16];
#pragma unroll
            for (int j = 0; j < 4; j++) {
                ulonglong2 v = arow[j];
                a2[j * 2] = v.x;
                a2[j * 2 + 1] = v.y;
            }
            float b[8];
            *(float4*)&b[0] = *(const float4*)&Bs[buf][k][tx * 8];
            *(float4*)&b[4] = *(const float4*)&Bs[buf][k][tx * 8 + 4];
            unsigned long long bp[8];
#pragma unroll
            for (int c = 0; c < 8; c++) bp[c] = pack2(b[c]);
#pragma unroll
            for (int rp2 = 0; rp2 < 8; rp2++)
#pragma unroll
                for (int c = 0; c < 8; c++) ffma2(acc[rp2][c], a2[rp2], bp[c]);
        }
    }
    __syncthreads();   // all As/Bs reads done before vsm overwrites the region

    // ---- LN epilogue -> swizzled vsm[k][r ^ ((k>>3&7)<<2)] ----
    {
        float b2av[8], b2ev[8], gv[8], bbv[8];
        *(float4*)&b2av[0] = *(const float4*)&b2a[col0];
        *(float4*)&b2av[4] = *(const float4*)&b2a[col0 + 4];
        *(float4*)&b2ev[0] = *(const float4*)&b2e[col0];
        *(float4*)&b2ev[4] = *(const float4*)&b2e[col0 + 4];
        *(float4*)&gv[0] = *(const float4*)&lng[col0];
        *(float4*)&gv[4] = *(const float4*)&lng[col0 + 4];
        *(float4*)&bbv[0] = *(const float4*)&lnb[col0];
        *(float4*)&bbv[4] = *(const float4*)&lnb[col0 + 4];
        int swzst = (tx & 7) << 2;
#pragma unroll
        for (int rp2 = 0; rp2 < 8; rp2++) {
            float vlo[8], vhi[8];
#pragma unroll
            for (int c = 0; c < 8; c++) unpack2(acc[rp2][c], vlo[c], vhi[c]);
#pragma unroll
            for (int h2 = 0; h2 < 2; h2++) {
                int rl = ty * 16 + rp2 * 2 + h2;
                int gr = row0 + rl;
                bool valid = gr < NN;
                float da = valid ? dega[gr] : 0.f;
                float de = valid ? dege[gr] : 0.f;
                float rs[8];
                if (valid) {
                    *(float4*)&rs[0] = *(const float4*)&resid[(size_t)gr * H + col0];
                    *(float4*)&rs[4] = *(const float4*)&resid[(size_t)gr * H + col0 + 4];
                } else {
#pragma unroll
                    for (int c = 0; c < 8; c++) rs[c] = 0.f;
                }
                float* vv = h2 ? vhi : vlo;
                float v[8];
                float s = 0.f, s2 = 0.f;
#pragma unroll
                for (int c = 0; c < 8; c++) {
                    v[c] = vv[c] + rs[c] + da * b2av[c] + de * b2ev[c];
                    s += v[c];
                    s2 += v[c] * v[c];
                }
#pragma unroll
                for (int off = 8; off; off >>= 1) {
                    s += __shfl_xor_sync(0xffffffffu, s, off);
                    s2 += __shfl_xor_sync(0xffffffffu, s2, off);
                }
                float mu = s * (1.f / 128.f);
                float var = s2 * (1.f / 128.f) - mu * mu;
                float rstd = rsqrtf(var + 1e-5f);
                int rsw = rl ^ swzst;
#pragma unroll
                for (int c = 0; c < 8; c++) {
                    float o = (v[c] - mu) * rstd * gv[c] + bbv[c];
                    vsm[(col0 + c) * 128 + rsw] = o;
                }
            }
        }
    }
    __syncthreads();

    // ---- second GEMM: out = vsm @ Wc (K=128), then out = v + relu(.+bc) ----
#pragma unroll
    for (int rp2 = 0; rp2 < 8; rp2++)
#pragma unroll
        for (int c = 0; c < 8; c++) acc[rp2][c] = 0ull;

    for (int it2 = 0; it2 < 4; it2++) {
        int buf = it2 & 1;
        asm volatile("cp.async.wait_group 0;" ::: "memory");
        __syncthreads();
        if (it2 + 1 < 4) {
            int kk = (it2 + 1) * BK;
            uint32_t bb = bs2_base + (unsigned)((buf ^ 1) * BK * BN) * 4u;
#pragma unroll
            for (int i = 0; i < 4; i++) {
                int k = bk0 + i * 8;
                const float* s = Wc + (size_t)(kk + k) * H + bc8;
                uint32_t d = bb + (unsigned)(k * BN + bc8) * 4u;
                cp16(d, s);
                cp16(d + 16, s + 4);
            }
            asm volatile("cp.async.commit_group;" ::: "memory");
        }
#pragma unroll 4
        for (int k = 0; k < BK; k++) {
            int kk = it2 * BK + k;
            int swzk = ((kk >> 3) & 7) << 2;
            unsigned long long a2[8];
#pragma unroll
            for (int j = 0; j < 4; j++) {
                ulonglong2 v = *(const ulonglong2*)&vsm[kk * 128 + ((ty * 16 + j * 4) ^ swzk)];
                a2[j * 2] = v.x;
                a2[j * 2 + 1] = v.y;
            }
            float b[8];
            *(float4*)&b[0] = *(const float4*)&Bs2[buf][k][tx * 8];
            *(float4*)&b[4] = *(const float4*)&Bs2[buf][k][tx * 8 + 4];
            unsigned long long bp[8];
#pragma unroll
            for (int c = 0; c < 8; c++) bp[c] = pack2(b[c]);
#pragma unroll
            for (int rp2 = 0; rp2 < 8; rp2++)
#pragma unroll
                for (int c = 0; c < 8; c++) ffma2(acc[rp2][c], a2[rp2], bp[c]);
        }
    }

    // epilogue: out = v + relu(acc + bc)
    {
        float bv[8];
#pragma unroll
        for (int c = 0; c < 8; c++) bv[c] = bc[col0 + c];
        int swzst = (tx & 7) << 2;
#pragma unroll
        for (int rp2 = 0; rp2 < 8; rp2++) {
            float vlo[8], vhi[8];
#pragma unroll
            for (int c = 0; c < 8; c++) unpack2(acc[rp2][c], vlo[c], vhi[c]);
#pragma unroll
            for (int h2 = 0; h2 < 2; h2++) {
                int rl = ty * 16 + rp2 * 2 + h2;
                int gr = row0 + rl;
                if (gr < NN) {
                    const float* v = h2 ? vhi : vlo;
                    int rsw = rl ^ swzst;
                    float o[8];
#pragma unroll
                    for (int c = 0; c < 8; c++) {
                        float vres = vsm[(col0 + c) * 128 + rsw];
                        o[c] = vres + fmaxf(v[c] + bv[c], 0.f);
                    }
                    *(float4*)&out[(size_t)gr * H + col0] = *(float4*)o;
                    *(float4*)&out[(size_t)gr * H + col0 + 4] = *(float4*)(o + 4);
                }
            }
        }
    }
}

// ---------------- launch ----------------
extern "C" void kernel_launch(void* const* d_in, const int* in_sizes, int n_in,
                              void* d_out, int out_size) {
    (void)in_sizes; (void)n_in; (void)out_size;
    const float* x       = (const float*)d_in[0];
    const int*   ally_ei = (const int*)d_in[1];
    const float* ally_ea = (const float*)d_in[2];
    const int*   enc_ei  = (const int*)d_in[3];
    const float* enc_ea  = (const float*)d_in[4];
    const float* W_in    = (const float*)d_in[5];
    const float* b_in    = (const float*)d_in[6];
    const float* ally_W1 = (const float*)d_in[7];
    const float* ally_b1 = (const float*)d_in[8];
    const float* ally_W2 = (const float*)d_in[9];
    const float* ally_b2 = (const float*)d_in[10];
    const float* enc_W1  = (const float*)d_in[11];
    const float* enc_b1  = (const float*)d_in[12];
    const float* enc_W2  = (const float*)d_in[13];
    const float* enc_b2  = (const float*)d_in[14];
    const float* ln_g    = (const float*)d_in[15];
    const float* ln_b    = (const float*)d_in[16];
    const float* comb_W  = (const float*)d_in[17];
    const float* comb_b  = (const float*)d_in[18];
    float* out = (float*)d_out;

    float *h, *PQ, *S, *deg;
    int *cnt, *rp, *cur, *bsum;
    float4* edges;
    cudaGetSymbolAddress((void**)&h, g_h);
    cudaGetSymbolAddress((void**)&PQ, g_PQ);
    cudaGetSymbolAddress((void**)&S, g_S);
    cudaGetSymbolAddress((void**)&deg, g_deg);
    cudaGetSymbolAddress((void**)&cnt, g_cnt);
    cudaGetSymbolAddress((void**)&rp, g_rp);
    cudaGetSymbolAddress((void**)&cur, g_cur);
    cudaGetSymbolAddress((void**)&bsum, g_bsum);
    cudaGetSymbolAddress((void**)&edges, g_edges);
    float* dega = deg;
    float* dege = deg + NN;

    const int SMEM = (2 * BK * (BM + 4) + 2 * BK * BN) * 4;  // 66560 B
    const int SMEM12 = SM12_FLOATS * 4;                      // 99328 B
    cudaFuncSetAttribute(gemm0_kernel, cudaFuncAttributeMaxDynamicSharedMemorySize, SMEM);
    cudaFuncSetAttribute(gemm12_kernel, cudaFuncAttributeMaxDynamicSharedMemorySize, SMEM12);

    const int nblk = (NN + BM - 1) / BM;  // 782

    // ---- CSR build (once; shared by both layers) ----
    fill_zero<<<64, 256>>>((float4*)cnt, N2 / 4);
    hist_kernel<<<(2 * NE + 255) / 256, 256>>>(ally_ei, enc_ei, cnt);
    scan1<<<NB1, SCB>>>(cnt, rp, bsum);
    scan2<<<1, SCB>>>(bsum);
    scan3<<<NB1, SCB>>>(cnt, rp, bsum, cur, deg);
    fill_csr<<<(2 * NE + 255) / 256, 256>>>(ally_ei, ally_ea, enc_ei, enc_ea, cur, edges);

    // input projection
    input_proj<<<NN / IPN, 128>>>(x, W_in, b_in, h);

    for (int i = 0; i < 2; i++) {
        const float* aW1 = ally_W1 + (size_t)i * 258 * H;
        const float* eW1 = enc_W1 + (size_t)i * 258 * H;

        // P/Q for both edge types
        gemm0_kernel<<<dim3(nblk, 4), 128, SMEM>>>(
            h, aW1, aW1 + 128 * H, eW1, eW1 + 128 * H,
            ally_b1 + i * H, enc_b1 + i * H, PQ);

        // CSR edge pass
        edge_csr<<<N2 / 8, 256>>>(rp, edges, PQ, aW1 + 256 * H, eW1 + 256 * H, S);

        // fused combine + LN + comb MLP
        float* dst = (i == 1) ? out : h;
        gemm12_kernel<<<nblk, 128, SMEM12>>>(
            S,
            ally_W2 + (size_t)i * H * H, enc_W2 + (size_t)i * H * H,
            comb_W + (size_t)i * H * H, comb_b + i * H,
            h, dega, dege,
            ally_b2 + i * H, enc_b2 + i * H,
            ln_g + i * H, ln_b + i * H,
            dst);
    }
}